// round 13
// baseline (speedup 1.0000x reference)
#include <cuda_runtime.h>
#include <cuda_bf16.h>
#include <cstdint>

// Problem constants
#define BB   4
#define NN   1024
#define DM   256
#define LL   768          // MAX_VIS
#define DI   512          // D_INNER
#define DS   16           // D_STATE
#define DTR  16           // DT_RANK
#define MROWS (BB*LL)     // 3072
#define DEPTH 12
#define TCH  48           // scan chunk length
#define KCH  16           // chunks (TCH*KCH == LL)

// ---------------- scratch (device globals; no allocation allowed) ----------
__device__ __align__(16) float g_hid [MROWS*DM];
__device__ __align__(16) float g_res [MROWS*DM];
__device__ __align__(16) float g_norm[MROWS*DM];
__device__ __align__(16) float g_xz  [MROWS*2*DI];
__device__ __align__(16) float g_xc  [MROWS*DI];
__device__ __align__(16) float g_xdbl[MROWS*48];
__device__ __align__(16) float g_dt  [MROWS*DI];
__device__ __align__(16) float g_e1  [MROWS*DI];
__device__ __align__(16) float g_pq  [BB*DI*KCH*32];
__device__ __align__(16) float g_hin [BB*KCH*DI*DS];
__device__ __align__(16) float g_y   [MROWS*DI];
__device__ int   g_src[BB*LL];
__device__ int   g_maskflag;
__device__ int   g_afast;

// ---------------- helpers ---------------------------------------------------
__device__ __forceinline__ float block_sum_256(float v) {
    __shared__ float sh[8];
    __syncthreads();
#pragma unroll
    for (int o = 16; o; o >>= 1) v += __shfl_xor_sync(0xffffffffu, v, o);
    if ((threadIdx.x & 31) == 0) sh[threadIdx.x >> 5] = v;
    __syncthreads();
    float t = 0.f;
#pragma unroll
    for (int i = 0; i < 8; i++) t += sh[i];
    return t;
}

__device__ __forceinline__ float silu_fast(float x) { return x / (1.f + __expf(-x)); }

// binary-power table dA[s] = e1^(s+1), s=0..15
__device__ __forceinline__ void pow_table(float e1, float* dA) {
    float e2 = e1*e1, e4 = e2*e2, e8 = e4*e4;
    dA[0]=e1;        dA[1]=e2;       dA[2]=e2*e1;     dA[3]=e4;
    dA[4]=e4*e1;     dA[5]=e4*e2;    dA[6]=dA[5]*e1;  dA[7]=e8;
    dA[8]=e8*e1;     dA[9]=e8*e2;    dA[10]=dA[9]*e1; dA[11]=e8*e4;
    dA[12]=dA[11]*e1; dA[13]=dA[11]*e2; dA[14]=dA[13]*e1; dA[15]=e8*e8;
}

// ---------------- mask dtype detection + flags init -------------------------
__global__ void detect_mask_kernel(const unsigned char* __restrict__ m) {
    int lane = threadIdx.x;
    int s = 0;
    for (int i = lane; i < 4096; i += 32) s += m[i];
#pragma unroll
    for (int o = 16; o; o >>= 1) s += __shfl_xor_sync(0xffffffffu, s, o);
    if (lane == 0) {
        int f;
        if (s == 256)        f = 1;   // int32
        else if (s == 48896) f = 2;   // float32
        else                 f = 0;   // bytes
        g_maskflag = f;
        g_afast = 1;
    }
}

// ---------------- A-structure check: A_s == (s+1)*A_1 ? ---------------------
__global__ void check_A_kernel(const float* __restrict__ Alog, int n) {
    int i = blockIdx.x * blockDim.x + threadIdx.x;
    if (i >= n) return;
    int s = i & 15;
    float A1 = expf(Alog[i - s]);
    float As = expf(Alog[i]);
    if (fabsf(As - (float)(s+1)*A1) > 1e-4f * fabsf(As))
        atomicExch(&g_afast, 0);
}

// ---------------- gather index build (stable compaction order) --------------
__global__ void gather_idx_kernel(const void* __restrict__ maskraw) {
    __shared__ int sscan[NN];
    int b = blockIdx.x, t = threadIdx.x;
    int flag = g_maskflag;
    int mv;
    if (flag == 1)      mv = ((const int*)maskraw)[b*NN + t] != 0;
    else if (flag == 2) mv = ((const float*)maskraw)[b*NN + t] != 0.f;
    else                mv = ((const unsigned char*)maskraw)[b*NN + t] != 0;
    int keep = !mv;
    sscan[t] = keep;
    __syncthreads();
    for (int off = 1; off < NN; off <<= 1) {
        int v = sscan[t];
        if (t >= off) v += sscan[t - off];
        __syncthreads();
        sscan[t] = v;
        __syncthreads();
    }
    if (keep) {
        int pos = sscan[t] - 1;
        if (pos < LL) g_src[b*LL + pos] = t;
    }
}

// ---------------- gather copy: one block per visible row --------------------
__global__ void gather_copy_kernel(const float* __restrict__ tokens) {
    int row = blockIdx.x;
    int b = row / LL;
    int src = g_src[row];
    int c = threadIdx.x;
    g_hid[(size_t)row*DM + c] = tokens[((size_t)b*NN + src)*DM + c];
    g_res[(size_t)row*DM + c] = 0.f;
}

// ---------------- residual add + rmsnorm (warp per row) ---------------------
__global__ __launch_bounds__(256)
void resid_rmsnorm_kernel(const float* __restrict__ w) {
    const int warp = threadIdx.x >> 5, lane = threadIdx.x & 31;
    const int row = blockIdx.x * 8 + warp;
    const size_t base = (size_t)row*DM + lane*8;
    float4 h0 = *(const float4*)&g_hid[base];
    float4 h1 = *(const float4*)&g_hid[base+4];
    float4 r0 = *(const float4*)&g_res[base];
    float4 r1 = *(const float4*)&g_res[base+4];
    r0.x += h0.x; r0.y += h0.y; r0.z += h0.z; r0.w += h0.w;
    r1.x += h1.x; r1.y += h1.y; r1.z += h1.z; r1.w += h1.w;
    *(float4*)&g_res[base]   = r0;
    *(float4*)&g_res[base+4] = r1;
    float ss = r0.x*r0.x + r0.y*r0.y + r0.z*r0.z + r0.w*r0.w
             + r1.x*r1.x + r1.y*r1.y + r1.z*r1.z + r1.w*r1.w;
#pragma unroll
    for (int o = 16; o; o >>= 1) ss += __shfl_xor_sync(0xffffffffu, ss, o);
    float rs = rsqrtf(ss * (1.f/DM) + 1e-5f);
    float4 w0 = __ldg((const float4*)&w[lane*8]);
    float4 w1 = __ldg((const float4*)&w[lane*8+4]);
    float4 o0 = make_float4(r0.x*rs*w0.x, r0.y*rs*w0.y, r0.z*rs*w0.z, r0.w*rs*w0.w);
    float4 o1 = make_float4(r1.x*rs*w1.x, r1.y*rs*w1.y, r1.z*rs*w1.z, r1.w*rs*w1.w);
    *(float4*)&g_norm[base]   = o0;
    *(float4*)&g_norm[base+4] = o1;
}

// ---------------- double-buffered SGEMM: C[M,N] = A[M,K] * B[N,K]^T ---------
template<int BM, int BN>
__global__ __launch_bounds__(256, 2)
void sgemm_nt(const float* __restrict__ A, const float* __restrict__ B,
              float* __restrict__ C, int M, int N, int K) {
    constexpr int RC = BM / 64;
    constexpr int CC = BN / 64;
    __shared__ float As[2][8][BM];
    __shared__ float Bs[2][8][BN];
    const int tid = threadIdx.x;
    const int tx = tid & 15, ty = tid >> 4;
    const int m0 = blockIdx.y * BM, n0 = blockIdx.x * BN;

    float acc[RC*4][CC*4];
#pragma unroll
    for (int i = 0; i < RC*4; i++)
#pragma unroll
        for (int j = 0; j < CC*4; j++) acc[i][j] = 0.f;

    const bool hasA = tid < BM*2;
    const bool hasB = tid < BN*2;
    const int arow = tid >> 1, akc = (tid & 1) * 4;

    if (hasA) {
        float4 v = *(const float4*)&A[(size_t)(m0+arow)*K + akc];
        As[0][akc+0][arow]=v.x; As[0][akc+1][arow]=v.y;
        As[0][akc+2][arow]=v.z; As[0][akc+3][arow]=v.w;
    }
    if (hasB) {
        float4 v = *(const float4*)&B[(size_t)(n0+arow)*K + akc];
        Bs[0][akc+0][arow]=v.x; Bs[0][akc+1][arow]=v.y;
        Bs[0][akc+2][arow]=v.z; Bs[0][akc+3][arow]=v.w;
    }
    __syncthreads();

    const int nkt = K >> 3;
    int buf = 0;
    for (int kt = 0; kt < nkt; kt++) {
        float4 va, vb;
        const bool more = (kt + 1) < nkt;
        if (more) {
            int k0n = (kt + 1) << 3;
            if (hasA) va = *(const float4*)&A[(size_t)(m0+arow)*K + k0n + akc];
            if (hasB) vb = *(const float4*)&B[(size_t)(n0+arow)*K + k0n + akc];
        }
#pragma unroll
        for (int k = 0; k < 8; k++) {
            float4 a4[RC], b4[CC];
#pragma unroll
            for (int rc = 0; rc < RC; rc++)
                a4[rc] = *(const float4*)&As[buf][k][rc*64 + ty*4];
#pragma unroll
            for (int cc = 0; cc < CC; cc++)
                b4[cc] = *(const float4*)&Bs[buf][k][cc*64 + tx*4];
#pragma unroll
            for (int rc = 0; rc < RC; rc++) {
                const float ar[4] = {a4[rc].x, a4[rc].y, a4[rc].z, a4[rc].w};
#pragma unroll
                for (int i = 0; i < 4; i++)
#pragma unroll
                    for (int cc = 0; cc < CC; cc++) {
                        acc[rc*4+i][cc*4+0] += ar[i] * b4[cc].x;
                        acc[rc*4+i][cc*4+1] += ar[i] * b4[cc].y;
                        acc[rc*4+i][cc*4+2] += ar[i] * b4[cc].z;
                        acc[rc*4+i][cc*4+3] += ar[i] * b4[cc].w;
                    }
            }
        }
        if (more) {
            int nb = buf ^ 1;
            if (hasA) {
                As[nb][akc+0][arow]=va.x; As[nb][akc+1][arow]=va.y;
                As[nb][akc+2][arow]=va.z; As[nb][akc+3][arow]=va.w;
            }
            if (hasB) {
                Bs[nb][akc+0][arow]=vb.x; Bs[nb][akc+1][arow]=vb.y;
                Bs[nb][akc+2][arow]=vb.z; Bs[nb][akc+3][arow]=vb.w;
            }
            __syncthreads();
            buf = nb;
        }
    }

#pragma unroll
    for (int rc = 0; rc < RC; rc++)
#pragma unroll
        for (int i = 0; i < 4; i++) {
            int m = m0 + rc*64 + ty*4 + i;
#pragma unroll
            for (int cc = 0; cc < CC; cc++) {
                float4 o = make_float4(acc[rc*4+i][cc*4+0], acc[rc*4+i][cc*4+1],
                                       acc[rc*4+i][cc*4+2], acc[rc*4+i][cc*4+3]);
                *(float4*)&C[(size_t)m*N + n0 + cc*64 + tx*4] = o;
            }
        }
}

// ---------------- fused conv+silu+x_proj -------------------------------------
__global__ __launch_bounds__(256)
void xproj_conv_kernel(const float* __restrict__ xw,
                       const float* __restrict__ cw,
                       const float* __restrict__ cb) {
    __shared__ float As[16][129];
    __shared__ float Bs[48][129];
    const int tid = threadIdx.x;
    const int m0 = blockIdx.x * 16;
    const int row = tid >> 4, col0 = tid & 15;
    float acc0 = 0.f, acc1 = 0.f, acc2 = 0.f;
    for (int kc = 0; kc < DI; kc += 128) {
#pragma unroll
        for (int i = tid; i < 16*32; i += 256) {
            int r = i >> 5, cj = (i & 31) << 2;
            int d = kc + cj;
            int m = m0 + r;
            int t = m % LL;
            const float* xzp = g_xz + (size_t)m*(2*DI) + d;
            float4 x0 = *(const float4*)xzp;
            float4 x1 = make_float4(0,0,0,0), x2 = x1, x3 = x1;
            if (t >= 1) x1 = *(const float4*)(xzp -   2*DI);
            if (t >= 2) x2 = *(const float4*)(xzp - 2*2*DI);
            if (t >= 3) x3 = *(const float4*)(xzp - 3*2*DI);
            float4 cw0 = *(const float4*)&cw[(d+0)*4];
            float4 cw1 = *(const float4*)&cw[(d+1)*4];
            float4 cw2 = *(const float4*)&cw[(d+2)*4];
            float4 cw3 = *(const float4*)&cw[(d+3)*4];
            float4 cbv = *(const float4*)&cb[d];
            float4 o;
            o.x = cbv.x + cw0.w*x0.x + cw0.z*x1.x + cw0.y*x2.x + cw0.x*x3.x;
            o.y = cbv.y + cw1.w*x0.y + cw1.z*x1.y + cw1.y*x2.y + cw1.x*x3.y;
            o.z = cbv.z + cw2.w*x0.z + cw2.z*x1.z + cw2.y*x2.z + cw2.x*x3.z;
            o.w = cbv.w + cw3.w*x0.w + cw3.z*x1.w + cw3.y*x2.w + cw3.x*x3.w;
            o.x = silu_fast(o.x); o.y = silu_fast(o.y);
            o.z = silu_fast(o.z); o.w = silu_fast(o.w);
            As[r][cj]=o.x; As[r][cj+1]=o.y; As[r][cj+2]=o.z; As[r][cj+3]=o.w;
            *(float4*)&g_xc[(size_t)m*DI + d] = o;
        }
#pragma unroll
        for (int i = tid; i < 48*32; i += 256) {
            int r = i >> 5, c4 = (i & 31) << 2;
            float4 v = *(const float4*)&xw[(size_t)r*DI + kc + c4];
            Bs[r][c4]=v.x; Bs[r][c4+1]=v.y; Bs[r][c4+2]=v.z; Bs[r][c4+3]=v.w;
        }
        __syncthreads();
#pragma unroll 4
        for (int k = 0; k < 128; k++) {
            float a = As[row][k];
            acc0 += a * Bs[col0][k];
            acc1 += a * Bs[col0+16][k];
            acc2 += a * Bs[col0+32][k];
        }
        __syncthreads();
    }
    float* o = &g_xdbl[(size_t)(m0+row)*48];
    o[col0]      = acc0;
    o[col0+16]   = acc1;
    o[col0+32]   = acc2;
}

// ---------------- scan S1: per-chunk (P,Q) + dt + e1 -------------------------
__global__ __launch_bounds__(128)
void scan_s1_kernel(const float* __restrict__ Alog,
                    const float* __restrict__ dtw,
                    const float* __restrict__ dtb) {
    __shared__ __align__(16) float srow[TCH][32];   // [t][0:16)=dtr, [16:32)=B
    const int tid = threadIdx.x;
    const int d = blockIdx.x * 128 + tid;
    const int c = blockIdx.y;
    const int b = blockIdx.z;
    const int t0 = c * TCH;
    const int fast = g_afast;

    for (int i = tid; i < TCH*32; i += 128) {
        int t = i >> 5, j = i & 31;
        srow[t][j] = g_xdbl[((size_t)(b*LL + t0 + t))*48 + j];
    }

    float4 w0 = __ldg((const float4*)&dtw[d*DTR +  0]);
    float4 w1 = __ldg((const float4*)&dtw[d*DTR +  4]);
    float4 w2 = __ldg((const float4*)&dtw[d*DTR +  8]);
    float4 w3 = __ldg((const float4*)&dtw[d*DTR + 12]);
    const float bias = __ldg(&dtb[d]);
    const float A1 = -__expf(__ldg(&Alog[d*DS]));

    float Av[DS];
    if (!fast) {
#pragma unroll
        for (int s = 0; s < DS; s++) Av[s] = -__expf(__ldg(&Alog[d*DS + s]));
    }

    const float* xcp = g_xc + (size_t)(b*LL + t0)*DI + d;

    float P[DS], Q[DS];
#pragma unroll
    for (int s = 0; s < DS; s++) { P[s] = 1.f; Q[s] = 0.f; }
    float E = 1.f;

    __syncthreads();

    float xb[2][4];
#pragma unroll
    for (int k = 0; k < 4; k++) xb[0][k] = xcp[(size_t)k*DI];

    const int NG = TCH/4;
    for (int g = 0; g < NG; g++) {
        const int pb = g & 1;
        if (g + 1 < NG) {
#pragma unroll
            for (int k = 0; k < 4; k++)
                xb[pb^1][k] = xcp[(size_t)((g+1)*4 + k)*DI];
        }
#pragma unroll
        for (int k = 0; k < 4; k++) {
            const int t = g*4 + k;
            float4 r0 = *(const float4*)&srow[t][0];
            float4 r1 = *(const float4*)&srow[t][4];
            float4 r2 = *(const float4*)&srow[t][8];
            float4 r3 = *(const float4*)&srow[t][12];
            float v = bias
                + r0.x*w0.x + r0.y*w0.y + r0.z*w0.z + r0.w*w0.w
                + r1.x*w1.x + r1.y*w1.y + r1.z*w1.z + r1.w*w1.w
                + r2.x*w2.x + r2.y*w2.y + r2.z*w2.z + r2.w*w2.w
                + r3.x*w3.x + r3.y*w3.y + r3.z*w3.z + r3.w*w3.w;
            float dt = fmaxf(v, 0.f) + __logf(1.f + __expf(-fabsf(v)));
            size_t idx = (size_t)(b*LL + t0 + t)*DI + d;
            float xv = xb[pb][k];
            float cdt = dt * xv;
            g_dt[idx] = dt;
            float e1 = __expf(dt * A1);
            g_e1[idx] = e1;

            float4 b0 = *(const float4*)&srow[t][16];
            float4 b1 = *(const float4*)&srow[t][20];
            float4 b2 = *(const float4*)&srow[t][24];
            float4 b3 = *(const float4*)&srow[t][28];
            float Bv[DS] = {b0.x,b0.y,b0.z,b0.w, b1.x,b1.y,b1.z,b1.w,
                            b2.x,b2.y,b2.z,b2.w, b3.x,b3.y,b3.z,b3.w};

            if (fast) {
                float dA[DS];
                pow_table(e1, dA);
                E *= e1;
#pragma unroll
                for (int s = 0; s < DS; s++) Q[s] = dA[s]*Q[s] + cdt*Bv[s];
            } else {
#pragma unroll
                for (int s = 0; s < DS; s++) {
                    float dA = __expf(dt * Av[s]);
                    P[s] *= dA;
                    Q[s] = dA*Q[s] + cdt*Bv[s];
                }
            }
        }
    }
    if (fast) pow_table(E, P);

    float* pq = g_pq + ((size_t)(b*DI + d)*KCH + c)*32;
#pragma unroll
    for (int s = 0; s < DS; s += 4)
        *(float4*)&pq[s] = make_float4(P[s],P[s+1],P[s+2],P[s+3]);
#pragma unroll
    for (int s = 0; s < DS; s += 4)
        *(float4*)&pq[16+s] = make_float4(Q[s],Q[s+1],Q[s+2],Q[s+3]);
}

// ---------------- hin: chunk-prefix scan over (P,Q) --------------------------
__global__ __launch_bounds__(256)
void hin_kernel() {
    const int g = blockIdx.x * 256 + threadIdx.x;   // 0..BB*DI*DS-1
    const int s = g & 15;
    const int d = (g >> 4) & (DI-1);
    const int b = g >> 13;
    const float* pqb = g_pq + ((size_t)(b*DI + d)*KCH)*32;
    float h = 0.f;
#pragma unroll
    for (int cc = 0; cc < KCH; cc++) {
        g_hin[((size_t)(b*KCH + cc)*DI + d)*DS + s] = h;
        float P = pqb[cc*32 + s];
        float Q = pqb[cc*32 + 16 + s];
        h = P*h + Q;
    }
}

// ---------------- scan S2: load h_in, rescan chunk, emit y -------------------
__global__ __launch_bounds__(128)
void scan_s2_kernel(const float* __restrict__ Alog,
                    const float* __restrict__ Dsk) {
    __shared__ __align__(16) float srow[TCH][32];   // [t][0:16)=B, [16:32)=C
    const int tid = threadIdx.x;
    const int d = blockIdx.x * 128 + tid;
    const int c = blockIdx.y;
    const int b = blockIdx.z;
    const int t0 = c * TCH;
    const int fast = g_afast;
    const float Dd = __ldg(&Dsk[d]);

    for (int i = tid; i < TCH*32; i += 128) {
        int t = i >> 5, j = i & 31;
        srow[t][j] = g_xdbl[((size_t)(b*LL + t0 + t))*48 + 16 + j];
    }

    float Av[DS];
    if (!fast) {
#pragma unroll
        for (int s = 0; s < DS; s++) Av[s] = -__expf(__ldg(&Alog[d*DS + s]));
    }

    float h[DS];
    {
        const float* hp = g_hin + ((size_t)(b*KCH + c)*DI + d)*DS;
#pragma unroll
        for (int s = 0; s < DS; s += 4) {
            float4 v = *(const float4*)&hp[s];
            h[s]=v.x; h[s+1]=v.y; h[s+2]=v.z; h[s+3]=v.w;
        }
    }

    const size_t sbase = (size_t)(b*LL + t0)*DI + d;
    const float* dtp = g_dt + sbase;
    const float* xcp = g_xc + sbase;
    const float* e1p = g_e1 + sbase;
    const float* zp  = g_xz + (size_t)(b*LL + t0)*(2*DI) + DI + d;
    float*       yp  = g_y  + sbase;

    __syncthreads();

    float dtb_[2][4], xcb[2][4], e1b[2][4], zb[2][4];
#pragma unroll
    for (int k = 0; k < 4; k++) {
        dtb_[0][k] = dtp[(size_t)k*DI];
        xcb [0][k] = xcp[(size_t)k*DI];
        e1b [0][k] = e1p[(size_t)k*DI];
        zb  [0][k] = zp [(size_t)k*2*DI];
    }

    const int NG = TCH/4;
    for (int g = 0; g < NG; g++) {
        const int pb = g & 1;
        if (g + 1 < NG) {
#pragma unroll
            for (int k = 0; k < 4; k++) {
                const size_t o = (size_t)((g+1)*4 + k)*DI;
                dtb_[pb^1][k] = dtp[o];
                xcb [pb^1][k] = xcp[o];
                e1b [pb^1][k] = e1p[o];
                zb  [pb^1][k] = zp [2*o];
            }
        }
#pragma unroll
        for (int k = 0; k < 4; k++) {
            const int t = g*4 + k;
            float dt = dtb_[pb][k];
            float xv = xcb[pb][k];
            float cdt = dt * xv;

            float4 b0 = *(const float4*)&srow[t][0];
            float4 b1 = *(const float4*)&srow[t][4];
            float4 b2 = *(const float4*)&srow[t][8];
            float4 b3 = *(const float4*)&srow[t][12];
            float4 c0 = *(const float4*)&srow[t][16];
            float4 c1 = *(const float4*)&srow[t][20];
            float4 c2 = *(const float4*)&srow[t][24];
            float4 c3 = *(const float4*)&srow[t][28];
            float Bv[DS] = {b0.x,b0.y,b0.z,b0.w, b1.x,b1.y,b1.z,b1.w,
                            b2.x,b2.y,b2.z,b2.w, b3.x,b3.y,b3.z,b3.w};
            float Cv[DS] = {c0.x,c0.y,c0.z,c0.w, c1.x,c1.y,c1.z,c1.w,
                            c2.x,c2.y,c2.z,c2.w, c3.x,c3.y,c3.z,c3.w};

            float dA[DS];
            if (fast) {
                pow_table(e1b[pb][k], dA);
            } else {
#pragma unroll
                for (int s = 0; s < DS; s++) dA[s] = __expf(dt * Av[s]);
            }
            float p = 0.f;
#pragma unroll
            for (int s = 0; s < DS; s++) {
                h[s] = dA[s]*h[s] + cdt*Bv[s];
                p += h[s]*Cv[s];
            }
            float zv = zb[pb][k];
            yp[(size_t)t*DI] = (p + Dd*xv) * silu_fast(zv);
        }
    }
}

// ---------------- final: rmsnorm + layernorm + output layout ----------------
__global__ void final_kernel(const float* __restrict__ wf,
                             const float* __restrict__ lw,
                             const float* __restrict__ lb,
                             float* __restrict__ out) {
    int row = blockIdx.x, c = threadIdx.x;
    size_t idx = (size_t)row*DM + c;
    float h = g_hid[idx] + g_res[idx];
    float ss = block_sum_256(h*h);
    h = h * rsqrtf(ss * (1.f/DM) + 1e-5f) * wf[c];
    float mu = block_sum_256(h) * (1.f/DM);
    float hm = h - mu;
    float var = block_sum_256(hm*hm) * (1.f/DM);
    float o = hm * rsqrtf(var + 1e-5f) * lw[c] + lb[c];
    int b = row / LL, t = row % LL;
    size_t dst = (t < LL-1) ? ((size_t)(b*(LL-1) + t)*DM + c)
                            : ((size_t)BB*(LL-1)*DM + (size_t)b*DM + c);
    out[dst] = o;
}

// ---------------- host launch -----------------------------------------------
static float* sym_addr(const void* sym) {
    void* p = nullptr;
    cudaGetSymbolAddress(&p, sym);
    return (float*)p;
}

extern "C" void kernel_launch(void* const* d_in, const int* in_sizes, int n_in,
                              void* d_out, int out_size) {
    const float* tokens = (const float*)d_in[0];
    const void*  mask   = d_in[1];
    const float* in_w   = (const float*)d_in[2];
    const float* conv_w = (const float*)d_in[3];
    const float* conv_b = (const float*)d_in[4];
    const float* x_w    = (const float*)d_in[5];
    const float* dtw    = (const float*)d_in[6];
    const float* dtb    = (const float*)d_in[7];
    const float* Alog   = (const float*)d_in[8];
    const float* Dsk    = (const float*)d_in[9];
    const float* out_w  = (const float*)d_in[10];
    const float* norm_w = (const float*)d_in[11];
    const float* norm_f = (const float*)d_in[12];
    const float* ln_w   = (const float*)d_in[13];
    const float* ln_b   = (const float*)d_in[14];
    float* out = (float*)d_out;

    float* p_norm = sym_addr(g_norm);
    float* p_xz   = sym_addr(g_xz);
    float* p_y    = sym_addr(g_y);
    float* p_hid  = sym_addr(g_hid);

    detect_mask_kernel<<<1, 32>>>((const unsigned char*)mask);
    {
        int n = DEPTH*DI*DS;
        check_A_kernel<<<(n + 255)/256, 256>>>(Alog, n);
    }
    gather_idx_kernel<<<BB, NN>>>(mask);
    gather_copy_kernel<<<MROWS, DM>>>(tokens);

    dim3 sgrid(DI/128, KCH, BB);

    for (int l = 0; l < DEPTH; l++) {
        resid_rmsnorm_kernel<<<MROWS/8, 256>>>(norm_w + (size_t)l*DM);

        // xz = norm @ in_w^T   (3072 x 1024 x 256) — 128x64 tiles, 384 CTAs
        {
            dim3 grid((2*DI)/64, MROWS/128);
            sgemm_nt<128,64><<<grid, 256>>>(p_norm, in_w + (size_t)l*2*DI*DM,
                                            p_xz, MROWS, 2*DI, DM);
        }

        // fused conv+silu+x_proj: writes g_xc and g_xdbl
        xproj_conv_kernel<<<MROWS/16, 256>>>(x_w + (size_t)l*48*DI,
                                             conv_w + (size_t)l*DI*4,
                                             conv_b + (size_t)l*DI);

        // scan: S1 (P,Q,dt,e1), hin (chunk-prefix), S2 (rescan + gate)
        scan_s1_kernel<<<sgrid, 128>>>(Alog + (size_t)l*DI*DS,
                                       dtw  + (size_t)l*DI*DTR,
                                       dtb  + (size_t)l*DI);
        hin_kernel<<<(BB*DI*DS)/256, 256>>>();
        scan_s2_kernel<<<sgrid, 128>>>(Alog + (size_t)l*DI*DS,
                                       Dsk  + (size_t)l*DI);

        // hidden = y @ out_w^T (3072 x 256 x 512)
        {
            dim3 grid(DM/64, MROWS/64);
            sgemm_nt<64,64><<<grid, 256>>>(p_y, out_w + (size_t)l*DM*DI,
                                           p_hid, MROWS, DM, DI);
        }
    }

    final_kernel<<<MROWS, DM>>>(norm_f, ln_w, ln_b, out);
}

// round 14
// speedup vs baseline: 1.0321x; 1.0321x over previous
#include <cuda_runtime.h>
#include <cuda_bf16.h>
#include <cstdint>

// Problem constants
#define BB   4
#define NN   1024
#define DM   256
#define LL   768          // MAX_VIS
#define DI   512          // D_INNER
#define DS   16           // D_STATE
#define DTR  16           // DT_RANK
#define MROWS (BB*LL)     // 3072
#define DEPTH 12
#define TCH  48           // scan chunk length
#define KCH  16           // chunks (TCH*KCH == LL)

// ---------------- scratch (device globals; no allocation allowed) ----------
__device__ __align__(16) float g_res [MROWS*DM];   // running residual
__device__ __align__(16) float g_xz  [MROWS*2*DI];
__device__ __align__(16) float g_xc  [MROWS*DI];
__device__ __align__(16) float g_xdbl[MROWS*48];
__device__ __align__(16) float g_dt  [MROWS*DI];
__device__ __align__(16) float g_e1  [MROWS*DI];
__device__ __align__(16) float g_pq  [BB*DI*KCH*32];
__device__ __align__(16) float g_hin [BB*KCH*DI*DS];
__device__ __align__(16) float g_y   [MROWS*DI];
__device__ int   g_src[BB*LL];
__device__ int   g_maskflag;
__device__ int   g_afast;

// ---------------- helpers ---------------------------------------------------
__device__ __forceinline__ float block_sum_256(float v) {
    __shared__ float sh[8];
    __syncthreads();
#pragma unroll
    for (int o = 16; o; o >>= 1) v += __shfl_xor_sync(0xffffffffu, v, o);
    if ((threadIdx.x & 31) == 0) sh[threadIdx.x >> 5] = v;
    __syncthreads();
    float t = 0.f;
#pragma unroll
    for (int i = 0; i < 8; i++) t += sh[i];
    return t;
}

__device__ __forceinline__ float silu_fast(float x) { return x / (1.f + __expf(-x)); }

// binary-power table dA[s] = e1^(s+1), s=0..15
__device__ __forceinline__ void pow_table(float e1, float* dA) {
    float e2 = e1*e1, e4 = e2*e2, e8 = e4*e4;
    dA[0]=e1;        dA[1]=e2;       dA[2]=e2*e1;     dA[3]=e4;
    dA[4]=e4*e1;     dA[5]=e4*e2;    dA[6]=dA[5]*e1;  dA[7]=e8;
    dA[8]=e8*e1;     dA[9]=e8*e2;    dA[10]=dA[9]*e1; dA[11]=e8*e4;
    dA[12]=dA[11]*e1; dA[13]=dA[11]*e2; dA[14]=dA[13]*e1; dA[15]=e8*e8;
}

// ---------------- mask dtype detection + flags init -------------------------
__global__ void detect_mask_kernel(const unsigned char* __restrict__ m) {
    int lane = threadIdx.x;
    int s = 0;
    for (int i = lane; i < 4096; i += 32) s += m[i];
#pragma unroll
    for (int o = 16; o; o >>= 1) s += __shfl_xor_sync(0xffffffffu, s, o);
    if (lane == 0) {
        int f;
        if (s == 256)        f = 1;   // int32
        else if (s == 48896) f = 2;   // float32
        else                 f = 0;   // bytes
        g_maskflag = f;
        g_afast = 1;
    }
}

// ---------------- A-structure check: A_s == (s+1)*A_1 ? ---------------------
__global__ void check_A_kernel(const float* __restrict__ Alog, int n) {
    int i = blockIdx.x * blockDim.x + threadIdx.x;
    if (i >= n) return;
    int s = i & 15;
    float A1 = expf(Alog[i - s]);
    float As = expf(Alog[i]);
    if (fabsf(As - (float)(s+1)*A1) > 1e-4f * fabsf(As))
        atomicExch(&g_afast, 0);
}

// ---------------- gather index build (stable compaction order) --------------
__global__ void gather_idx_kernel(const void* __restrict__ maskraw) {
    __shared__ int sscan[NN];
    int b = blockIdx.x, t = threadIdx.x;
    int flag = g_maskflag;
    int mv;
    if (flag == 1)      mv = ((const int*)maskraw)[b*NN + t] != 0;
    else if (flag == 2) mv = ((const float*)maskraw)[b*NN + t] != 0.f;
    else                mv = ((const unsigned char*)maskraw)[b*NN + t] != 0;
    int keep = !mv;
    sscan[t] = keep;
    __syncthreads();
    for (int off = 1; off < NN; off <<= 1) {
        int v = sscan[t];
        if (t >= off) v += sscan[t - off];
        __syncthreads();
        sscan[t] = v;
        __syncthreads();
    }
    if (keep) {
        int pos = sscan[t] - 1;
        if (pos < LL) g_src[b*LL + pos] = t;
    }
}

// ---------------- gather copy: residual_0 = visible tokens ------------------
__global__ void gather_copy_kernel(const float* __restrict__ tokens) {
    int row = blockIdx.x;
    int b = row / LL;
    int src = g_src[row];
    int c = threadIdx.x;
    g_res[(size_t)row*DM + c] = tokens[((size_t)b*NN + src)*DM + c];
}

// ---------------- in_proj GEMM with fused rmsnorm ----------------------------
// C[M, 2*DI] = rmsnorm(g_res)[M, DM] @ B[2*DI, DM]^T
// Prepass computes per-row rsqrt(mean sq) into smem; A loads scale on the fly.
__global__ __launch_bounds__(256, 2)
void inproj_gemm(const float* __restrict__ B, const float* __restrict__ nw,
                 float* __restrict__ C) {
    constexpr int BM = 128, BN = 128, Kk = DM, Nn = 2*DI;
    __shared__ float As[2][8][BM];
    __shared__ float Bs[2][8][BN];
    __shared__ float sscale[BM];
    const int tid = threadIdx.x;
    const int tx = tid & 15, ty = tid >> 4;
    const int m0 = blockIdx.y * BM, n0 = blockIdx.x * BN;

    // prepass: 2 threads per row compute sum of squares over DM=256
    {
        const int pr = tid >> 1, ph = tid & 1;
        const float* rp = g_res + (size_t)(m0 + pr)*DM + ph*128;
        float ss = 0.f;
#pragma unroll
        for (int i = 0; i < 32; i++) {
            float4 v = *(const float4*)(rp + i*4);
            ss += v.x*v.x + v.y*v.y + v.z*v.z + v.w*v.w;
        }
        ss += __shfl_xor_sync(0xffffffffu, ss, 1);
        if (ph == 0) sscale[pr] = rsqrtf(ss * (1.f/DM) + 1e-5f);
    }
    __syncthreads();

    float acc[8][8];
#pragma unroll
    for (int i = 0; i < 8; i++)
#pragma unroll
        for (int j = 0; j < 8; j++) acc[i][j] = 0.f;

    const int arow = tid >> 1, akc = (tid & 1) * 4;
    const float rsc = sscale[arow];

    // load tile 0 (A scaled by rs*norm_w)
    {
        float4 v = *(const float4*)&g_res[(size_t)(m0+arow)*Kk + akc];
        float4 w = __ldg((const float4*)&nw[akc]);
        As[0][akc+0][arow]=v.x*rsc*w.x; As[0][akc+1][arow]=v.y*rsc*w.y;
        As[0][akc+2][arow]=v.z*rsc*w.z; As[0][akc+3][arow]=v.w*rsc*w.w;
        float4 bv = *(const float4*)&B[(size_t)(n0+arow)*Kk + akc];
        Bs[0][akc+0][arow]=bv.x; Bs[0][akc+1][arow]=bv.y;
        Bs[0][akc+2][arow]=bv.z; Bs[0][akc+3][arow]=bv.w;
    }
    __syncthreads();

    const int nkt = Kk >> 3;
    int buf = 0;
    for (int kt = 0; kt < nkt; kt++) {
        float4 va, vb, vw;
        const bool more = (kt + 1) < nkt;
        if (more) {
            int k0n = (kt + 1) << 3;
            va = *(const float4*)&g_res[(size_t)(m0+arow)*Kk + k0n + akc];
            vb = *(const float4*)&B[(size_t)(n0+arow)*Kk + k0n + akc];
            vw = __ldg((const float4*)&nw[k0n + akc]);
        }
#pragma unroll
        for (int k = 0; k < 8; k++) {
            float4 a4[2], b4[2];
#pragma unroll
            for (int rc = 0; rc < 2; rc++)
                a4[rc] = *(const float4*)&As[buf][k][rc*64 + ty*4];
#pragma unroll
            for (int cc = 0; cc < 2; cc++)
                b4[cc] = *(const float4*)&Bs[buf][k][cc*64 + tx*4];
#pragma unroll
            for (int rc = 0; rc < 2; rc++) {
                const float ar[4] = {a4[rc].x, a4[rc].y, a4[rc].z, a4[rc].w};
#pragma unroll
                for (int i = 0; i < 4; i++)
#pragma unroll
                    for (int cc = 0; cc < 2; cc++) {
                        acc[rc*4+i][cc*4+0] += ar[i] * b4[cc].x;
                        acc[rc*4+i][cc*4+1] += ar[i] * b4[cc].y;
                        acc[rc*4+i][cc*4+2] += ar[i] * b4[cc].z;
                        acc[rc*4+i][cc*4+3] += ar[i] * b4[cc].w;
                    }
            }
        }
        if (more) {
            int nb = buf ^ 1;
            As[nb][akc+0][arow]=va.x*rsc*vw.x; As[nb][akc+1][arow]=va.y*rsc*vw.y;
            As[nb][akc+2][arow]=va.z*rsc*vw.z; As[nb][akc+3][arow]=va.w*rsc*vw.w;
            Bs[nb][akc+0][arow]=vb.x; Bs[nb][akc+1][arow]=vb.y;
            Bs[nb][akc+2][arow]=vb.z; Bs[nb][akc+3][arow]=vb.w;
            __syncthreads();
            buf = nb;
        }
    }

#pragma unroll
    for (int rc = 0; rc < 2; rc++)
#pragma unroll
        for (int i = 0; i < 4; i++) {
            int m = m0 + rc*64 + ty*4 + i;
#pragma unroll
            for (int cc = 0; cc < 2; cc++) {
                float4 o = make_float4(acc[rc*4+i][cc*4+0], acc[rc*4+i][cc*4+1],
                                       acc[rc*4+i][cc*4+2], acc[rc*4+i][cc*4+3]);
                *(float4*)&C[(size_t)m*Nn + n0 + cc*64 + tx*4] = o;
            }
        }
}

// ---------------- out_proj GEMM: g_res += g_y @ out_w^T ----------------------
__global__ __launch_bounds__(256, 2)
void outproj_gemm(const float* __restrict__ A, const float* __restrict__ B) {
    constexpr int BM = 64, BN = 64, Kk = DI, Nn = DM;
    __shared__ float As[2][8][BM];
    __shared__ float Bs[2][8][BN];
    const int tid = threadIdx.x;
    const int tx = tid & 15, ty = tid >> 4;
    const int m0 = blockIdx.y * BM, n0 = blockIdx.x * BN;

    float acc[4][4];
#pragma unroll
    for (int i = 0; i < 4; i++)
#pragma unroll
        for (int j = 0; j < 4; j++) acc[i][j] = 0.f;

    const bool hasL = tid < BM*2;   // 128 loader threads (BM==BN==64)
    const int arow = tid >> 1, akc = (tid & 1) * 4;

    if (hasL) {
        float4 v = *(const float4*)&A[(size_t)(m0+arow)*Kk + akc];
        As[0][akc+0][arow]=v.x; As[0][akc+1][arow]=v.y;
        As[0][akc+2][arow]=v.z; As[0][akc+3][arow]=v.w;
        float4 b = *(const float4*)&B[(size_t)(n0+arow)*Kk + akc];
        Bs[0][akc+0][arow]=b.x; Bs[0][akc+1][arow]=b.y;
        Bs[0][akc+2][arow]=b.z; Bs[0][akc+3][arow]=b.w;
    }
    __syncthreads();

    const int nkt = Kk >> 3;
    int buf = 0;
    for (int kt = 0; kt < nkt; kt++) {
        float4 va, vb;
        const bool more = (kt + 1) < nkt;
        if (more && hasL) {
            int k0n = (kt + 1) << 3;
            va = *(const float4*)&A[(size_t)(m0+arow)*Kk + k0n + akc];
            vb = *(const float4*)&B[(size_t)(n0+arow)*Kk + k0n + akc];
        }
#pragma unroll
        for (int k = 0; k < 8; k++) {
            float4 a4 = *(const float4*)&As[buf][k][ty*4];
            float4 b4 = *(const float4*)&Bs[buf][k][tx*4];
            const float ar[4] = {a4.x, a4.y, a4.z, a4.w};
#pragma unroll
            for (int i = 0; i < 4; i++) {
                acc[i][0] += ar[i] * b4.x;
                acc[i][1] += ar[i] * b4.y;
                acc[i][2] += ar[i] * b4.z;
                acc[i][3] += ar[i] * b4.w;
            }
        }
        if (more) {
            int nb = buf ^ 1;
            if (hasL) {
                As[nb][akc+0][arow]=va.x; As[nb][akc+1][arow]=va.y;
                As[nb][akc+2][arow]=va.z; As[nb][akc+3][arow]=va.w;
                Bs[nb][akc+0][arow]=vb.x; Bs[nb][akc+1][arow]=vb.y;
                Bs[nb][akc+2][arow]=vb.z; Bs[nb][akc+3][arow]=vb.w;
            }
            __syncthreads();
            buf = nb;
        }
    }

#pragma unroll
    for (int i = 0; i < 4; i++) {
        int m = m0 + ty*4 + i;
        float* cp = &g_res[(size_t)m*Nn + n0 + tx*4];
        float4 old = *(const float4*)cp;
        old.x += acc[i][0]; old.y += acc[i][1];
        old.z += acc[i][2]; old.w += acc[i][3];
        *(float4*)cp = old;
    }
}

// ---------------- fused conv+silu+x_proj -------------------------------------
__global__ __launch_bounds__(256)
void xproj_conv_kernel(const float* __restrict__ xw,
                       const float* __restrict__ cw,
                       const float* __restrict__ cb) {
    __shared__ float As[16][129];
    __shared__ float Bs[48][129];
    const int tid = threadIdx.x;
    const int m0 = blockIdx.x * 16;
    const int row = tid >> 4, col0 = tid & 15;
    float acc0 = 0.f, acc1 = 0.f, acc2 = 0.f;
    for (int kc = 0; kc < DI; kc += 128) {
#pragma unroll
        for (int i = tid; i < 16*32; i += 256) {
            int r = i >> 5, cj = (i & 31) << 2;
            int d = kc + cj;
            int m = m0 + r;
            int t = m % LL;
            const float* xzp = g_xz + (size_t)m*(2*DI) + d;
            float4 x0 = *(const float4*)xzp;
            float4 x1 = make_float4(0,0,0,0), x2 = x1, x3 = x1;
            if (t >= 1) x1 = *(const float4*)(xzp -   2*DI);
            if (t >= 2) x2 = *(const float4*)(xzp - 2*2*DI);
            if (t >= 3) x3 = *(const float4*)(xzp - 3*2*DI);
            float4 cw0 = *(const float4*)&cw[(d+0)*4];
            float4 cw1 = *(const float4*)&cw[(d+1)*4];
            float4 cw2 = *(const float4*)&cw[(d+2)*4];
            float4 cw3 = *(const float4*)&cw[(d+3)*4];
            float4 cbv = *(const float4*)&cb[d];
            float4 o;
            o.x = cbv.x + cw0.w*x0.x + cw0.z*x1.x + cw0.y*x2.x + cw0.x*x3.x;
            o.y = cbv.y + cw1.w*x0.y + cw1.z*x1.y + cw1.y*x2.y + cw1.x*x3.y;
            o.z = cbv.z + cw2.w*x0.z + cw2.z*x1.z + cw2.y*x2.z + cw2.x*x3.z;
            o.w = cbv.w + cw3.w*x0.w + cw3.z*x1.w + cw3.y*x2.w + cw3.x*x3.w;
            o.x = silu_fast(o.x); o.y = silu_fast(o.y);
            o.z = silu_fast(o.z); o.w = silu_fast(o.w);
            As[r][cj]=o.x; As[r][cj+1]=o.y; As[r][cj+2]=o.z; As[r][cj+3]=o.w;
            *(float4*)&g_xc[(size_t)m*DI + d] = o;
        }
#pragma unroll
        for (int i = tid; i < 48*32; i += 256) {
            int r = i >> 5, c4 = (i & 31) << 2;
            float4 v = *(const float4*)&xw[(size_t)r*DI + kc + c4];
            Bs[r][c4]=v.x; Bs[r][c4+1]=v.y; Bs[r][c4+2]=v.z; Bs[r][c4+3]=v.w;
        }
        __syncthreads();
#pragma unroll 4
        for (int k = 0; k < 128; k++) {
            float a = As[row][k];
            acc0 += a * Bs[col0][k];
            acc1 += a * Bs[col0+16][k];
            acc2 += a * Bs[col0+32][k];
        }
        __syncthreads();
    }
    float* o = &g_xdbl[(size_t)(m0+row)*48];
    o[col0]      = acc0;
    o[col0+16]   = acc1;
    o[col0+32]   = acc2;
}

// ---------------- scan S1: per-chunk (P,Q) + dt + e1 -------------------------
__global__ __launch_bounds__(128)
void scan_s1_kernel(const float* __restrict__ Alog,
                    const float* __restrict__ dtw,
                    const float* __restrict__ dtb) {
    __shared__ __align__(16) float srow[TCH][32];   // [t][0:16)=dtr, [16:32)=B
    const int tid = threadIdx.x;
    const int d = blockIdx.x * 128 + tid;
    const int c = blockIdx.y;
    const int b = blockIdx.z;
    const int t0 = c * TCH;
    const int fast = g_afast;

    for (int i = tid; i < TCH*32; i += 128) {
        int t = i >> 5, j = i & 31;
        srow[t][j] = g_xdbl[((size_t)(b*LL + t0 + t))*48 + j];
    }

    float4 w0 = __ldg((const float4*)&dtw[d*DTR +  0]);
    float4 w1 = __ldg((const float4*)&dtw[d*DTR +  4]);
    float4 w2 = __ldg((const float4*)&dtw[d*DTR +  8]);
    float4 w3 = __ldg((const float4*)&dtw[d*DTR + 12]);
    const float bias = __ldg(&dtb[d]);
    const float A1 = -__expf(__ldg(&Alog[d*DS]));

    float Av[DS];
    if (!fast) {
#pragma unroll
        for (int s = 0; s < DS; s++) Av[s] = -__expf(__ldg(&Alog[d*DS + s]));
    }

    const float* xcp = g_xc + (size_t)(b*LL + t0)*DI + d;

    float P[DS], Q[DS];
#pragma unroll
    for (int s = 0; s < DS; s++) { P[s] = 1.f; Q[s] = 0.f; }
    float E = 1.f;

    __syncthreads();

    float xb[2][4];
#pragma unroll
    for (int k = 0; k < 4; k++) xb[0][k] = xcp[(size_t)k*DI];

    const int NG = TCH/4;
    for (int g = 0; g < NG; g++) {
        const int pb = g & 1;
        if (g + 1 < NG) {
#pragma unroll
            for (int k = 0; k < 4; k++)
                xb[pb^1][k] = xcp[(size_t)((g+1)*4 + k)*DI];
        }
#pragma unroll
        for (int k = 0; k < 4; k++) {
            const int t = g*4 + k;
            float4 r0 = *(const float4*)&srow[t][0];
            float4 r1 = *(const float4*)&srow[t][4];
            float4 r2 = *(const float4*)&srow[t][8];
            float4 r3 = *(const float4*)&srow[t][12];
            float v = bias
                + r0.x*w0.x + r0.y*w0.y + r0.z*w0.z + r0.w*w0.w
                + r1.x*w1.x + r1.y*w1.y + r1.z*w1.z + r1.w*w1.w
                + r2.x*w2.x + r2.y*w2.y + r2.z*w2.z + r2.w*w2.w
                + r3.x*w3.x + r3.y*w3.y + r3.z*w3.z + r3.w*w3.w;
            float dt = fmaxf(v, 0.f) + __logf(1.f + __expf(-fabsf(v)));
            size_t idx = (size_t)(b*LL + t0 + t)*DI + d;
            float xv = xb[pb][k];
            float cdt = dt * xv;
            g_dt[idx] = dt;
            float e1 = __expf(dt * A1);
            g_e1[idx] = e1;

            float4 b0 = *(const float4*)&srow[t][16];
            float4 b1 = *(const float4*)&srow[t][20];
            float4 b2 = *(const float4*)&srow[t][24];
            float4 b3 = *(const float4*)&srow[t][28];
            float Bv[DS] = {b0.x,b0.y,b0.z,b0.w, b1.x,b1.y,b1.z,b1.w,
                            b2.x,b2.y,b2.z,b2.w, b3.x,b3.y,b3.z,b3.w};

            if (fast) {
                float dA[DS];
                pow_table(e1, dA);
                E *= e1;
#pragma unroll
                for (int s = 0; s < DS; s++) Q[s] = dA[s]*Q[s] + cdt*Bv[s];
            } else {
#pragma unroll
                for (int s = 0; s < DS; s++) {
                    float dA = __expf(dt * Av[s]);
                    P[s] *= dA;
                    Q[s] = dA*Q[s] + cdt*Bv[s];
                }
            }
        }
    }
    if (fast) pow_table(E, P);

    float* pq = g_pq + ((size_t)(b*DI + d)*KCH + c)*32;
#pragma unroll
    for (int s = 0; s < DS; s += 4)
        *(float4*)&pq[s] = make_float4(P[s],P[s+1],P[s+2],P[s+3]);
#pragma unroll
    for (int s = 0; s < DS; s += 4)
        *(float4*)&pq[16+s] = make_float4(Q[s],Q[s+1],Q[s+2],Q[s+3]);
}

// ---------------- hin: chunk-prefix scan over (P,Q) --------------------------
__global__ __launch_bounds__(256)
void hin_kernel() {
    const int g = blockIdx.x * 256 + threadIdx.x;   // 0..BB*DI*DS-1
    const int s = g & 15;
    const int d = (g >> 4) & (DI-1);
    const int b = g >> 13;
    const float* pqb = g_pq + ((size_t)(b*DI + d)*KCH)*32;
    float h = 0.f;
#pragma unroll
    for (int cc = 0; cc < KCH; cc++) {
        g_hin[((size_t)(b*KCH + cc)*DI + d)*DS + s] = h;
        float P = pqb[cc*32 + s];
        float Q = pqb[cc*32 + 16 + s];
        h = P*h + Q;
    }
}

// ---------------- scan S2: load h_in, rescan chunk, emit y -------------------
__global__ __launch_bounds__(128)
void scan_s2_kernel(const float* __restrict__ Alog,
                    const float* __restrict__ Dsk) {
    __shared__ __align__(16) float srow[TCH][32];   // [t][0:16)=B, [16:32)=C
    const int tid = threadIdx.x;
    const int d = blockIdx.x * 128 + tid;
    const int c = blockIdx.y;
    const int b = blockIdx.z;
    const int t0 = c * TCH;
    const int fast = g_afast;
    const float Dd = __ldg(&Dsk[d]);

    for (int i = tid; i < TCH*32; i += 128) {
        int t = i >> 5, j = i & 31;
        srow[t][j] = g_xdbl[((size_t)(b*LL + t0 + t))*48 + 16 + j];
    }

    float Av[DS];
    if (!fast) {
#pragma unroll
        for (int s = 0; s < DS; s++) Av[s] = -__expf(__ldg(&Alog[d*DS + s]));
    }

    float h[DS];
    {
        const float* hp = g_hin + ((size_t)(b*KCH + c)*DI + d)*DS;
#pragma unroll
        for (int s = 0; s < DS; s += 4) {
            float4 v = *(const float4*)&hp[s];
            h[s]=v.x; h[s+1]=v.y; h[s+2]=v.z; h[s+3]=v.w;
        }
    }

    const size_t sbase = (size_t)(b*LL + t0)*DI + d;
    const float* dtp = g_dt + sbase;
    const float* xcp = g_xc + sbase;
    const float* e1p = g_e1 + sbase;
    const float* zp  = g_xz + (size_t)(b*LL + t0)*(2*DI) + DI + d;
    float*       yp  = g_y  + sbase;

    __syncthreads();

    float dtb_[2][4], xcb[2][4], e1b[2][4], zb[2][4];
#pragma unroll
    for (int k = 0; k < 4; k++) {
        dtb_[0][k] = dtp[(size_t)k*DI];
        xcb [0][k] = xcp[(size_t)k*DI];
        e1b [0][k] = e1p[(size_t)k*DI];
        zb  [0][k] = zp [(size_t)k*2*DI];
    }

    const int NG = TCH/4;
    for (int g = 0; g < NG; g++) {
        const int pb = g & 1;
        if (g + 1 < NG) {
#pragma unroll
            for (int k = 0; k < 4; k++) {
                const size_t o = (size_t)((g+1)*4 + k)*DI;
                dtb_[pb^1][k] = dtp[o];
                xcb [pb^1][k] = xcp[o];
                e1b [pb^1][k] = e1p[o];
                zb  [pb^1][k] = zp [2*o];
            }
        }
#pragma unroll
        for (int k = 0; k < 4; k++) {
            const int t = g*4 + k;
            float dt = dtb_[pb][k];
            float xv = xcb[pb][k];
            float cdt = dt * xv;

            float4 b0 = *(const float4*)&srow[t][0];
            float4 b1 = *(const float4*)&srow[t][4];
            float4 b2 = *(const float4*)&srow[t][8];
            float4 b3 = *(const float4*)&srow[t][12];
            float4 c0 = *(const float4*)&srow[t][16];
            float4 c1 = *(const float4*)&srow[t][20];
            float4 c2 = *(const float4*)&srow[t][24];
            float4 c3 = *(const float4*)&srow[t][28];
            float Bv[DS] = {b0.x,b0.y,b0.z,b0.w, b1.x,b1.y,b1.z,b1.w,
                            b2.x,b2.y,b2.z,b2.w, b3.x,b3.y,b3.z,b3.w};
            float Cv[DS] = {c0.x,c0.y,c0.z,c0.w, c1.x,c1.y,c1.z,c1.w,
                            c2.x,c2.y,c2.z,c2.w, c3.x,c3.y,c3.z,c3.w};

            float dA[DS];
            if (fast) {
                pow_table(e1b[pb][k], dA);
            } else {
#pragma unroll
                for (int s = 0; s < DS; s++) dA[s] = __expf(dt * Av[s]);
            }
            float p = 0.f;
#pragma unroll
            for (int s = 0; s < DS; s++) {
                h[s] = dA[s]*h[s] + cdt*Bv[s];
                p += h[s]*Cv[s];
            }
            float zv = zb[pb][k];
            yp[(size_t)t*DI] = (p + Dd*xv) * silu_fast(zv);
        }
    }
}

// ---------------- final: rmsnorm + layernorm + output layout ----------------
__global__ void final_kernel(const float* __restrict__ wf,
                             const float* __restrict__ lw,
                             const float* __restrict__ lb,
                             float* __restrict__ out) {
    int row = blockIdx.x, c = threadIdx.x;
    size_t idx = (size_t)row*DM + c;
    float h = g_res[idx];           // residual already includes final hidden
    float ss = block_sum_256(h*h);
    h = h * rsqrtf(ss * (1.f/DM) + 1e-5f) * wf[c];
    float mu = block_sum_256(h) * (1.f/DM);
    float hm = h - mu;
    float var = block_sum_256(hm*hm) * (1.f/DM);
    float o = hm * rsqrtf(var + 1e-5f) * lw[c] + lb[c];
    int b = row / LL, t = row % LL;
    size_t dst = (t < LL-1) ? ((size_t)(b*(LL-1) + t)*DM + c)
                            : ((size_t)BB*(LL-1)*DM + (size_t)b*DM + c);
    out[dst] = o;
}

// ---------------- host launch -----------------------------------------------
static float* sym_addr(const void* sym) {
    void* p = nullptr;
    cudaGetSymbolAddress(&p, sym);
    return (float*)p;
}

extern "C" void kernel_launch(void* const* d_in, const int* in_sizes, int n_in,
                              void* d_out, int out_size) {
    const float* tokens = (const float*)d_in[0];
    const void*  mask   = d_in[1];
    const float* in_w   = (const float*)d_in[2];
    const float* conv_w = (const float*)d_in[3];
    const float* conv_b = (const float*)d_in[4];
    const float* x_w    = (const float*)d_in[5];
    const float* dtw    = (const float*)d_in[6];
    const float* dtb    = (const float*)d_in[7];
    const float* Alog   = (const float*)d_in[8];
    const float* Dsk    = (const float*)d_in[9];
    const float* out_w  = (const float*)d_in[10];
    const float* norm_w = (const float*)d_in[11];
    const float* norm_f = (const float*)d_in[12];
    const float* ln_w   = (const float*)d_in[13];
    const float* ln_b   = (const float*)d_in[14];
    float* out = (float*)d_out;

    float* p_xz = sym_addr(g_xz);
    float* p_y  = sym_addr(g_y);

    detect_mask_kernel<<<1, 32>>>((const unsigned char*)mask);
    {
        int n = DEPTH*DI*DS;
        check_A_kernel<<<(n + 255)/256, 256>>>(Alog, n);
    }
    gather_idx_kernel<<<BB, NN>>>(mask);
    gather_copy_kernel<<<MROWS, DM>>>(tokens);

    dim3 sgrid(DI/128, KCH, BB);

    for (int l = 0; l < DEPTH; l++) {
        // xz = rmsnorm(res) @ in_w^T   (fused rmsnorm; 128x128 tiles)
        {
            dim3 grid((2*DI)/128, MROWS/128);
            inproj_gemm<<<grid, 256>>>(in_w + (size_t)l*2*DI*DM,
                                       norm_w + (size_t)l*DM, p_xz);
        }

        // fused conv+silu+x_proj: writes g_xc and g_xdbl
        xproj_conv_kernel<<<MROWS/16, 256>>>(x_w + (size_t)l*48*DI,
                                             conv_w + (size_t)l*DI*4,
                                             conv_b + (size_t)l*DI);

        // scan: S1 (P,Q,dt,e1), hin (chunk-prefix), S2 (rescan + gate)
        scan_s1_kernel<<<sgrid, 128>>>(Alog + (size_t)l*DI*DS,
                                       dtw  + (size_t)l*DI*DTR,
                                       dtb  + (size_t)l*DI);
        hin_kernel<<<(BB*DI*DS)/256, 256>>>();
        scan_s2_kernel<<<sgrid, 128>>>(Alog + (size_t)l*DI*DS,
                                       Dsk  + (size_t)l*DI);

        // res += y @ out_w^T   (residual update fused into epilogue)
        {
            dim3 grid(DM/64, MROWS/64);
            outproj_gemm<<<grid, 256>>>(p_y, out_w + (size_t)l*DM*DI);
        }
    }

    final_kernel<<<MROWS, DM>>>(norm_f, ln_w, ln_b, out);
}

// round 15
// speedup vs baseline: 1.0871x; 1.0533x over previous
#include <cuda_runtime.h>
#include <cuda_bf16.h>
#include <cstdint>

// Problem constants
#define BB   4
#define NN   1024
#define DM   256
#define LL   768          // MAX_VIS
#define DI   512          // D_INNER
#define DS   16           // D_STATE
#define DTR  16           // DT_RANK
#define MROWS (BB*LL)     // 3072
#define DEPTH 12
#define TCH  48           // scan chunk length
#define KCH  16           // chunks (TCH*KCH == LL)

// ---------------- scratch (device globals; no allocation allowed) ----------
__device__ __align__(16) float g_res [MROWS*DM];   // running residual
__device__ __align__(16) float g_norm[MROWS*DM];
__device__ __align__(16) float g_xz  [MROWS*2*DI];
__device__ __align__(16) float g_xc  [MROWS*DI];
__device__ __align__(16) float g_xdbl[MROWS*48];
__device__ __align__(16) float g_dt  [MROWS*DI];
__device__ __align__(16) float g_e1  [MROWS*DI];
__device__ __align__(16) float g_pq  [BB*DI*KCH*32];
__device__ __align__(16) float g_hin [BB*KCH*DI*DS];
__device__ __align__(16) float g_y   [MROWS*DI];
__device__ int   g_src[BB*LL];
__device__ int   g_maskflag;
__device__ int   g_afast;

// ---------------- helpers ---------------------------------------------------
__device__ __forceinline__ float block_sum_256(float v) {
    __shared__ float sh[8];
    __syncthreads();
#pragma unroll
    for (int o = 16; o; o >>= 1) v += __shfl_xor_sync(0xffffffffu, v, o);
    if ((threadIdx.x & 31) == 0) sh[threadIdx.x >> 5] = v;
    __syncthreads();
    float t = 0.f;
#pragma unroll
    for (int i = 0; i < 8; i++) t += sh[i];
    return t;
}

__device__ __forceinline__ float silu_fast(float x) { return x / (1.f + __expf(-x)); }

// binary-power table dA[s] = e1^(s+1), s=0..15
__device__ __forceinline__ void pow_table(float e1, float* dA) {
    float e2 = e1*e1, e4 = e2*e2, e8 = e4*e4;
    dA[0]=e1;        dA[1]=e2;       dA[2]=e2*e1;     dA[3]=e4;
    dA[4]=e4*e1;     dA[5]=e4*e2;    dA[6]=dA[5]*e1;  dA[7]=e8;
    dA[8]=e8*e1;     dA[9]=e8*e2;    dA[10]=dA[9]*e1; dA[11]=e8*e4;
    dA[12]=dA[11]*e1; dA[13]=dA[11]*e2; dA[14]=dA[13]*e1; dA[15]=e8*e8;
}

// ---------------- mask dtype detection + flags init -------------------------
__global__ void detect_mask_kernel(const unsigned char* __restrict__ m) {
    int lane = threadIdx.x;
    int s = 0;
    for (int i = lane; i < 4096; i += 32) s += m[i];
#pragma unroll
    for (int o = 16; o; o >>= 1) s += __shfl_xor_sync(0xffffffffu, s, o);
    if (lane == 0) {
        int f;
        if (s == 256)        f = 1;   // int32
        else if (s == 48896) f = 2;   // float32
        else                 f = 0;   // bytes
        g_maskflag = f;
        g_afast = 1;
    }
}

// ---------------- A-structure check: A_s == (s+1)*A_1 ? ---------------------
__global__ void check_A_kernel(const float* __restrict__ Alog, int n) {
    int i = blockIdx.x * blockDim.x + threadIdx.x;
    if (i >= n) return;
    int s = i & 15;
    float A1 = expf(Alog[i - s]);
    float As = expf(Alog[i]);
    if (fabsf(As - (float)(s+1)*A1) > 1e-4f * fabsf(As))
        atomicExch(&g_afast, 0);
}

// ---------------- gather index build (stable compaction order) --------------
__global__ void gather_idx_kernel(const void* __restrict__ maskraw) {
    __shared__ int sscan[NN];
    int b = blockIdx.x, t = threadIdx.x;
    int flag = g_maskflag;
    int mv;
    if (flag == 1)      mv = ((const int*)maskraw)[b*NN + t] != 0;
    else if (flag == 2) mv = ((const float*)maskraw)[b*NN + t] != 0.f;
    else                mv = ((const unsigned char*)maskraw)[b*NN + t] != 0;
    int keep = !mv;
    sscan[t] = keep;
    __syncthreads();
    for (int off = 1; off < NN; off <<= 1) {
        int v = sscan[t];
        if (t >= off) v += sscan[t - off];
        __syncthreads();
        sscan[t] = v;
        __syncthreads();
    }
    if (keep) {
        int pos = sscan[t] - 1;
        if (pos < LL) g_src[b*LL + pos] = t;
    }
}

// ---------------- gather copy: residual_0 = visible tokens ------------------
__global__ void gather_copy_kernel(const float* __restrict__ tokens) {
    int row = blockIdx.x;
    int b = row / LL;
    int src = g_src[row];
    int c = threadIdx.x;
    g_res[(size_t)row*DM + c] = tokens[((size_t)b*NN + src)*DM + c];
}

// ---------------- rmsnorm (warp per row): norm = rmsnorm(res)*w --------------
__global__ __launch_bounds__(256)
void rmsnorm_kernel(const float* __restrict__ w) {
    const int warp = threadIdx.x >> 5, lane = threadIdx.x & 31;
    const int row = blockIdx.x * 8 + warp;
    const size_t base = (size_t)row*DM + lane*8;
    float4 r0 = *(const float4*)&g_res[base];
    float4 r1 = *(const float4*)&g_res[base+4];
    float ss = r0.x*r0.x + r0.y*r0.y + r0.z*r0.z + r0.w*r0.w
             + r1.x*r1.x + r1.y*r1.y + r1.z*r1.z + r1.w*r1.w;
#pragma unroll
    for (int o = 16; o; o >>= 1) ss += __shfl_xor_sync(0xffffffffu, ss, o);
    float rs = rsqrtf(ss * (1.f/DM) + 1e-5f);
    float4 w0 = __ldg((const float4*)&w[lane*8]);
    float4 w1 = __ldg((const float4*)&w[lane*8+4]);
    float4 o0 = make_float4(r0.x*rs*w0.x, r0.y*rs*w0.y, r0.z*rs*w0.z, r0.w*rs*w0.w);
    float4 o1 = make_float4(r1.x*rs*w1.x, r1.y*rs*w1.y, r1.z*rs*w1.z, r1.w*rs*w1.w);
    *(float4*)&g_norm[base]   = o0;
    *(float4*)&g_norm[base+4] = o1;
}

// ---------------- double-buffered SGEMM: C[M,N] = A[M,K] * B[N,K]^T ---------
template<int BM, int BN>
__global__ __launch_bounds__(256, 2)
void sgemm_nt(const float* __restrict__ A, const float* __restrict__ B,
              float* __restrict__ C, int M, int N, int K) {
    constexpr int RC = BM / 64;
    constexpr int CC = BN / 64;
    __shared__ float As[2][8][BM];
    __shared__ float Bs[2][8][BN];
    const int tid = threadIdx.x;
    const int tx = tid & 15, ty = tid >> 4;
    const int m0 = blockIdx.y * BM, n0 = blockIdx.x * BN;

    float acc[RC*4][CC*4];
#pragma unroll
    for (int i = 0; i < RC*4; i++)
#pragma unroll
        for (int j = 0; j < CC*4; j++) acc[i][j] = 0.f;

    const bool hasA = tid < BM*2;
    const bool hasB = tid < BN*2;
    const int arow = tid >> 1, akc = (tid & 1) * 4;

    if (hasA) {
        float4 v = *(const float4*)&A[(size_t)(m0+arow)*K + akc];
        As[0][akc+0][arow]=v.x; As[0][akc+1][arow]=v.y;
        As[0][akc+2][arow]=v.z; As[0][akc+3][arow]=v.w;
    }
    if (hasB) {
        float4 v = *(const float4*)&B[(size_t)(n0+arow)*K + akc];
        Bs[0][akc+0][arow]=v.x; Bs[0][akc+1][arow]=v.y;
        Bs[0][akc+2][arow]=v.z; Bs[0][akc+3][arow]=v.w;
    }
    __syncthreads();

    const int nkt = K >> 3;
    int buf = 0;
    for (int kt = 0; kt < nkt; kt++) {
        float4 va, vb;
        const bool more = (kt + 1) < nkt;
        if (more) {
            int k0n = (kt + 1) << 3;
            if (hasA) va = *(const float4*)&A[(size_t)(m0+arow)*K + k0n + akc];
            if (hasB) vb = *(const float4*)&B[(size_t)(n0+arow)*K + k0n + akc];
        }
#pragma unroll
        for (int k = 0; k < 8; k++) {
            float4 a4[RC], b4[CC];
#pragma unroll
            for (int rc = 0; rc < RC; rc++)
                a4[rc] = *(const float4*)&As[buf][k][rc*64 + ty*4];
#pragma unroll
            for (int cc = 0; cc < CC; cc++)
                b4[cc] = *(const float4*)&Bs[buf][k][cc*64 + tx*4];
#pragma unroll
            for (int rc = 0; rc < RC; rc++) {
                const float ar[4] = {a4[rc].x, a4[rc].y, a4[rc].z, a4[rc].w};
#pragma unroll
                for (int i = 0; i < 4; i++)
#pragma unroll
                    for (int cc = 0; cc < CC; cc++) {
                        acc[rc*4+i][cc*4+0] += ar[i] * b4[cc].x;
                        acc[rc*4+i][cc*4+1] += ar[i] * b4[cc].y;
                        acc[rc*4+i][cc*4+2] += ar[i] * b4[cc].z;
                        acc[rc*4+i][cc*4+3] += ar[i] * b4[cc].w;
                    }
            }
        }
        if (more) {
            int nb = buf ^ 1;
            if (hasA) {
                As[nb][akc+0][arow]=va.x; As[nb][akc+1][arow]=va.y;
                As[nb][akc+2][arow]=va.z; As[nb][akc+3][arow]=va.w;
            }
            if (hasB) {
                Bs[nb][akc+0][arow]=vb.x; Bs[nb][akc+1][arow]=vb.y;
                Bs[nb][akc+2][arow]=vb.z; Bs[nb][akc+3][arow]=vb.w;
            }
            __syncthreads();
            buf = nb;
        }
    }

#pragma unroll
    for (int rc = 0; rc < RC; rc++)
#pragma unroll
        for (int i = 0; i < 4; i++) {
            int m = m0 + rc*64 + ty*4 + i;
#pragma unroll
            for (int cc = 0; cc < CC; cc++) {
                float4 o = make_float4(acc[rc*4+i][cc*4+0], acc[rc*4+i][cc*4+1],
                                       acc[rc*4+i][cc*4+2], acc[rc*4+i][cc*4+3]);
                *(float4*)&C[(size_t)m*N + n0 + cc*64 + tx*4] = o;
            }
        }
}

// ---------------- out_proj GEMM: g_res += g_y @ out_w^T ----------------------
__global__ __launch_bounds__(256, 2)
void outproj_gemm(const float* __restrict__ A, const float* __restrict__ B) {
    constexpr int BM = 64, BN = 64, Kk = DI, Nn = DM;
    __shared__ float As[2][8][BM];
    __shared__ float Bs[2][8][BN];
    const int tid = threadIdx.x;
    const int tx = tid & 15, ty = tid >> 4;
    const int m0 = blockIdx.y * BM, n0 = blockIdx.x * BN;

    float acc[4][4];
#pragma unroll
    for (int i = 0; i < 4; i++)
#pragma unroll
        for (int j = 0; j < 4; j++) acc[i][j] = 0.f;

    const bool hasL = tid < BM*2;   // 128 loader threads
    const int arow = tid >> 1, akc = (tid & 1) * 4;

    if (hasL) {
        float4 v = *(const float4*)&A[(size_t)(m0+arow)*Kk + akc];
        As[0][akc+0][arow]=v.x; As[0][akc+1][arow]=v.y;
        As[0][akc+2][arow]=v.z; As[0][akc+3][arow]=v.w;
        float4 b = *(const float4*)&B[(size_t)(n0+arow)*Kk + akc];
        Bs[0][akc+0][arow]=b.x; Bs[0][akc+1][arow]=b.y;
        Bs[0][akc+2][arow]=b.z; Bs[0][akc+3][arow]=b.w;
    }
    __syncthreads();

    const int nkt = Kk >> 3;
    int buf = 0;
    for (int kt = 0; kt < nkt; kt++) {
        float4 va, vb;
        const bool more = (kt + 1) < nkt;
        if (more && hasL) {
            int k0n = (kt + 1) << 3;
            va = *(const float4*)&A[(size_t)(m0+arow)*Kk + k0n + akc];
            vb = *(const float4*)&B[(size_t)(n0+arow)*Kk + k0n + akc];
        }
#pragma unroll
        for (int k = 0; k < 8; k++) {
            float4 a4 = *(const float4*)&As[buf][k][ty*4];
            float4 b4 = *(const float4*)&Bs[buf][k][tx*4];
            const float ar[4] = {a4.x, a4.y, a4.z, a4.w};
#pragma unroll
            for (int i = 0; i < 4; i++) {
                acc[i][0] += ar[i] * b4.x;
                acc[i][1] += ar[i] * b4.y;
                acc[i][2] += ar[i] * b4.z;
                acc[i][3] += ar[i] * b4.w;
            }
        }
        if (more) {
            int nb = buf ^ 1;
            if (hasL) {
                As[nb][akc+0][arow]=va.x; As[nb][akc+1][arow]=va.y;
                As[nb][akc+2][arow]=va.z; As[nb][akc+3][arow]=va.w;
                Bs[nb][akc+0][arow]=vb.x; Bs[nb][akc+1][arow]=vb.y;
                Bs[nb][akc+2][arow]=vb.z; Bs[nb][akc+3][arow]=vb.w;
            }
            __syncthreads();
            buf = nb;
        }
    }

#pragma unroll
    for (int i = 0; i < 4; i++) {
        int m = m0 + ty*4 + i;
        float* cp = &g_res[(size_t)m*Nn + n0 + tx*4];
        float4 old = *(const float4*)cp;
        old.x += acc[i][0]; old.y += acc[i][1];
        old.z += acc[i][2]; old.w += acc[i][3];
        *(float4*)cp = old;
    }
}

// ---------------- fused conv+silu+x_proj -------------------------------------
__global__ __launch_bounds__(256)
void xproj_conv_kernel(const float* __restrict__ xw,
                       const float* __restrict__ cw,
                       const float* __restrict__ cb) {
    __shared__ float As[16][129];
    __shared__ float Bs[48][129];
    const int tid = threadIdx.x;
    const int m0 = blockIdx.x * 16;
    const int row = tid >> 4, col0 = tid & 15;
    float acc0 = 0.f, acc1 = 0.f, acc2 = 0.f;
    for (int kc = 0; kc < DI; kc += 128) {
#pragma unroll
        for (int i = tid; i < 16*32; i += 256) {
            int r = i >> 5, cj = (i & 31) << 2;
            int d = kc + cj;
            int m = m0 + r;
            int t = m % LL;
            const float* xzp = g_xz + (size_t)m*(2*DI) + d;
            float4 x0 = *(const float4*)xzp;
            float4 x1 = make_float4(0,0,0,0), x2 = x1, x3 = x1;
            if (t >= 1) x1 = *(const float4*)(xzp -   2*DI);
            if (t >= 2) x2 = *(const float4*)(xzp - 2*2*DI);
            if (t >= 3) x3 = *(const float4*)(xzp - 3*2*DI);
            float4 cw0 = *(const float4*)&cw[(d+0)*4];
            float4 cw1 = *(const float4*)&cw[(d+1)*4];
            float4 cw2 = *(const float4*)&cw[(d+2)*4];
            float4 cw3 = *(const float4*)&cw[(d+3)*4];
            float4 cbv = *(const float4*)&cb[d];
            float4 o;
            o.x = cbv.x + cw0.w*x0.x + cw0.z*x1.x + cw0.y*x2.x + cw0.x*x3.x;
            o.y = cbv.y + cw1.w*x0.y + cw1.z*x1.y + cw1.y*x2.y + cw1.x*x3.y;
            o.z = cbv.z + cw2.w*x0.z + cw2.z*x1.z + cw2.y*x2.z + cw2.x*x3.z;
            o.w = cbv.w + cw3.w*x0.w + cw3.z*x1.w + cw3.y*x2.w + cw3.x*x3.w;
            o.x = silu_fast(o.x); o.y = silu_fast(o.y);
            o.z = silu_fast(o.z); o.w = silu_fast(o.w);
            As[r][cj]=o.x; As[r][cj+1]=o.y; As[r][cj+2]=o.z; As[r][cj+3]=o.w;
            *(float4*)&g_xc[(size_t)m*DI + d] = o;
        }
#pragma unroll
        for (int i = tid; i < 48*32; i += 256) {
            int r = i >> 5, c4 = (i & 31) << 2;
            float4 v = *(const float4*)&xw[(size_t)r*DI + kc + c4];
            Bs[r][c4]=v.x; Bs[r][c4+1]=v.y; Bs[r][c4+2]=v.z; Bs[r][c4+3]=v.w;
        }
        __syncthreads();
#pragma unroll 4
        for (int k = 0; k < 128; k++) {
            float a = As[row][k];
            acc0 += a * Bs[col0][k];
            acc1 += a * Bs[col0+16][k];
            acc2 += a * Bs[col0+32][k];
        }
        __syncthreads();
    }
    float* o = &g_xdbl[(size_t)(m0+row)*48];
    o[col0]      = acc0;
    o[col0+16]   = acc1;
    o[col0+32]   = acc2;
}

// ---------------- scan S1: per-chunk (P,Q) + dt + e1 -------------------------
__global__ __launch_bounds__(128)
void scan_s1_kernel(const float* __restrict__ Alog,
                    const float* __restrict__ dtw,
                    const float* __restrict__ dtb) {
    __shared__ __align__(16) float srow[TCH][32];   // [t][0:16)=dtr, [16:32)=B
    const int tid = threadIdx.x;
    const int d = blockIdx.x * 128 + tid;
    const int c = blockIdx.y;
    const int b = blockIdx.z;
    const int t0 = c * TCH;
    const int fast = g_afast;

    for (int i = tid; i < TCH*32; i += 128) {
        int t = i >> 5, j = i & 31;
        srow[t][j] = g_xdbl[((size_t)(b*LL + t0 + t))*48 + j];
    }

    float4 w0 = __ldg((const float4*)&dtw[d*DTR +  0]);
    float4 w1 = __ldg((const float4*)&dtw[d*DTR +  4]);
    float4 w2 = __ldg((const float4*)&dtw[d*DTR +  8]);
    float4 w3 = __ldg((const float4*)&dtw[d*DTR + 12]);
    const float bias = __ldg(&dtb[d]);
    const float A1 = -__expf(__ldg(&Alog[d*DS]));

    float Av[DS];
    if (!fast) {
#pragma unroll
        for (int s = 0; s < DS; s++) Av[s] = -__expf(__ldg(&Alog[d*DS + s]));
    }

    const float* xcp = g_xc + (size_t)(b*LL + t0)*DI + d;

    float P[DS], Q[DS];
#pragma unroll
    for (int s = 0; s < DS; s++) { P[s] = 1.f; Q[s] = 0.f; }
    float E = 1.f;

    __syncthreads();

    float xb[2][4];
#pragma unroll
    for (int k = 0; k < 4; k++) xb[0][k] = xcp[(size_t)k*DI];

    const int NG = TCH/4;
    for (int g = 0; g < NG; g++) {
        const int pb = g & 1;
        if (g + 1 < NG) {
#pragma unroll
            for (int k = 0; k < 4; k++)
                xb[pb^1][k] = xcp[(size_t)((g+1)*4 + k)*DI];
        }
#pragma unroll
        for (int k = 0; k < 4; k++) {
            const int t = g*4 + k;
            float4 r0 = *(const float4*)&srow[t][0];
            float4 r1 = *(const float4*)&srow[t][4];
            float4 r2 = *(const float4*)&srow[t][8];
            float4 r3 = *(const float4*)&srow[t][12];
            float v = bias
                + r0.x*w0.x + r0.y*w0.y + r0.z*w0.z + r0.w*w0.w
                + r1.x*w1.x + r1.y*w1.y + r1.z*w1.z + r1.w*w1.w
                + r2.x*w2.x + r2.y*w2.y + r2.z*w2.z + r2.w*w2.w
                + r3.x*w3.x + r3.y*w3.y + r3.z*w3.z + r3.w*w3.w;
            float dt = fmaxf(v, 0.f) + __logf(1.f + __expf(-fabsf(v)));
            size_t idx = (size_t)(b*LL + t0 + t)*DI + d;
            float xv = xb[pb][k];
            float cdt = dt * xv;
            g_dt[idx] = dt;
            float e1 = __expf(dt * A1);
            g_e1[idx] = e1;

            float4 b0 = *(const float4*)&srow[t][16];
            float4 b1 = *(const float4*)&srow[t][20];
            float4 b2 = *(const float4*)&srow[t][24];
            float4 b3 = *(const float4*)&srow[t][28];
            float Bv[DS] = {b0.x,b0.y,b0.z,b0.w, b1.x,b1.y,b1.z,b1.w,
                            b2.x,b2.y,b2.z,b2.w, b3.x,b3.y,b3.z,b3.w};

            if (fast) {
                float dA[DS];
                pow_table(e1, dA);
                E *= e1;
#pragma unroll
                for (int s = 0; s < DS; s++) Q[s] = dA[s]*Q[s] + cdt*Bv[s];
            } else {
#pragma unroll
                for (int s = 0; s < DS; s++) {
                    float dA = __expf(dt * Av[s]);
                    P[s] *= dA;
                    Q[s] = dA*Q[s] + cdt*Bv[s];
                }
            }
        }
    }
    if (fast) pow_table(E, P);

    float* pq = g_pq + ((size_t)(b*DI + d)*KCH + c)*32;
#pragma unroll
    for (int s = 0; s < DS; s += 4)
        *(float4*)&pq[s] = make_float4(P[s],P[s+1],P[s+2],P[s+3]);
#pragma unroll
    for (int s = 0; s < DS; s += 4)
        *(float4*)&pq[16+s] = make_float4(Q[s],Q[s+1],Q[s+2],Q[s+3]);
}

// ---------------- hin: chunk-prefix scan over (P,Q) --------------------------
__global__ __launch_bounds__(256)
void hin_kernel() {
    const int g = blockIdx.x * 256 + threadIdx.x;   // 0..BB*DI*DS-1
    const int s = g & 15;
    const int d = (g >> 4) & (DI-1);
    const int b = g >> 13;
    const float* pqb = g_pq + ((size_t)(b*DI + d)*KCH)*32;
    float h = 0.f;
#pragma unroll
    for (int cc = 0; cc < KCH; cc++) {
        g_hin[((size_t)(b*KCH + cc)*DI + d)*DS + s] = h;
        float P = pqb[cc*32 + s];
        float Q = pqb[cc*32 + 16 + s];
        h = P*h + Q;
    }
}

// ---------------- scan S2: load h_in, rescan chunk, emit y -------------------
__global__ __launch_bounds__(128)
void scan_s2_kernel(const float* __restrict__ Alog,
                    const float* __restrict__ Dsk) {
    __shared__ __align__(16) float srow[TCH][32];   // [t][0:16)=B, [16:32)=C
    const int tid = threadIdx.x;
    const int d = blockIdx.x * 128 + tid;
    const int c = blockIdx.y;
    const int b = blockIdx.z;
    const int t0 = c * TCH;
    const int fast = g_afast;
    const float Dd = __ldg(&Dsk[d]);

    for (int i = tid; i < TCH*32; i += 128) {
        int t = i >> 5, j = i & 31;
        srow[t][j] = g_xdbl[((size_t)(b*LL + t0 + t))*48 + 16 + j];
    }

    float Av[DS];
    if (!fast) {
#pragma unroll
        for (int s = 0; s < DS; s++) Av[s] = -__expf(__ldg(&Alog[d*DS + s]));
    }

    float h[DS];
    {
        const float* hp = g_hin + ((size_t)(b*KCH + c)*DI + d)*DS;
#pragma unroll
        for (int s = 0; s < DS; s += 4) {
            float4 v = *(const float4*)&hp[s];
            h[s]=v.x; h[s+1]=v.y; h[s+2]=v.z; h[s+3]=v.w;
        }
    }

    const size_t sbase = (size_t)(b*LL + t0)*DI + d;
    const float* dtp = g_dt + sbase;
    const float* xcp = g_xc + sbase;
    const float* e1p = g_e1 + sbase;
    const float* zp  = g_xz + (size_t)(b*LL + t0)*(2*DI) + DI + d;
    float*       yp  = g_y  + sbase;

    __syncthreads();

    float dtb_[2][4], xcb[2][4], e1b[2][4], zb[2][4];
#pragma unroll
    for (int k = 0; k < 4; k++) {
        dtb_[0][k] = dtp[(size_t)k*DI];
        xcb [0][k] = xcp[(size_t)k*DI];
        e1b [0][k] = e1p[(size_t)k*DI];
        zb  [0][k] = zp [(size_t)k*2*DI];
    }

    const int NG = TCH/4;
    for (int g = 0; g < NG; g++) {
        const int pb = g & 1;
        if (g + 1 < NG) {
#pragma unroll
            for (int k = 0; k < 4; k++) {
                const size_t o = (size_t)((g+1)*4 + k)*DI;
                dtb_[pb^1][k] = dtp[o];
                xcb [pb^1][k] = xcp[o];
                e1b [pb^1][k] = e1p[o];
                zb  [pb^1][k] = zp [2*o];
            }
        }
#pragma unroll
        for (int k = 0; k < 4; k++) {
            const int t = g*4 + k;
            float dt = dtb_[pb][k];
            float xv = xcb[pb][k];
            float cdt = dt * xv;

            float4 b0 = *(const float4*)&srow[t][0];
            float4 b1 = *(const float4*)&srow[t][4];
            float4 b2 = *(const float4*)&srow[t][8];
            float4 b3 = *(const float4*)&srow[t][12];
            float4 c0 = *(const float4*)&srow[t][16];
            float4 c1 = *(const float4*)&srow[t][20];
            float4 c2 = *(const float4*)&srow[t][24];
            float4 c3 = *(const float4*)&srow[t][28];
            float Bv[DS] = {b0.x,b0.y,b0.z,b0.w, b1.x,b1.y,b1.z,b1.w,
                            b2.x,b2.y,b2.z,b2.w, b3.x,b3.y,b3.z,b3.w};
            float Cv[DS] = {c0.x,c0.y,c0.z,c0.w, c1.x,c1.y,c1.z,c1.w,
                            c2.x,c2.y,c2.z,c2.w, c3.x,c3.y,c3.z,c3.w};

            float dA[DS];
            if (fast) {
                pow_table(e1b[pb][k], dA);
            } else {
#pragma unroll
                for (int s = 0; s < DS; s++) dA[s] = __expf(dt * Av[s]);
            }
            float p = 0.f;
#pragma unroll
            for (int s = 0; s < DS; s++) {
                h[s] = dA[s]*h[s] + cdt*Bv[s];
                p += h[s]*Cv[s];
            }
            float zv = zb[pb][k];
            yp[(size_t)t*DI] = (p + Dd*xv) * silu_fast(zv);
        }
    }
}

// ---------------- final: rmsnorm + layernorm + output layout ----------------
__global__ void final_kernel(const float* __restrict__ wf,
                             const float* __restrict__ lw,
                             const float* __restrict__ lb,
                             float* __restrict__ out) {
    int row = blockIdx.x, c = threadIdx.x;
    size_t idx = (size_t)row*DM + c;
    float h = g_res[idx];           // residual already includes final hidden
    float ss = block_sum_256(h*h);
    h = h * rsqrtf(ss * (1.f/DM) + 1e-5f) * wf[c];
    float mu = block_sum_256(h) * (1.f/DM);
    float hm = h - mu;
    float var = block_sum_256(hm*hm) * (1.f/DM);
    float o = hm * rsqrtf(var + 1e-5f) * lw[c] + lb[c];
    int b = row / LL, t = row % LL;
    size_t dst = (t < LL-1) ? ((size_t)(b*(LL-1) + t)*DM + c)
                            : ((size_t)BB*(LL-1)*DM + (size_t)b*DM + c);
    out[dst] = o;
}

// ---------------- host launch -----------------------------------------------
static float* sym_addr(const void* sym) {
    void* p = nullptr;
    cudaGetSymbolAddress(&p, sym);
    return (float*)p;
}

extern "C" void kernel_launch(void* const* d_in, const int* in_sizes, int n_in,
                              void* d_out, int out_size) {
    const float* tokens = (const float*)d_in[0];
    const void*  mask   = d_in[1];
    const float* in_w   = (const float*)d_in[2];
    const float* conv_w = (const float*)d_in[3];
    const float* conv_b = (const float*)d_in[4];
    const float* x_w    = (const float*)d_in[5];
    const float* dtw    = (const float*)d_in[6];
    const float* dtb    = (const float*)d_in[7];
    const float* Alog   = (const float*)d_in[8];
    const float* Dsk    = (const float*)d_in[9];
    const float* out_w  = (const float*)d_in[10];
    const float* norm_w = (const float*)d_in[11];
    const float* norm_f = (const float*)d_in[12];
    const float* ln_w   = (const float*)d_in[13];
    const float* ln_b   = (const float*)d_in[14];
    float* out = (float*)d_out;

    float* p_norm = sym_addr(g_norm);
    float* p_xz   = sym_addr(g_xz);
    float* p_y    = sym_addr(g_y);

    detect_mask_kernel<<<1, 32>>>((const unsigned char*)mask);
    {
        int n = DEPTH*DI*DS;
        check_A_kernel<<<(n + 255)/256, 256>>>(Alog, n);
    }
    gather_idx_kernel<<<BB, NN>>>(mask);
    gather_copy_kernel<<<MROWS, DM>>>(tokens);

    dim3 sgrid(DI/128, KCH, BB);

    for (int l = 0; l < DEPTH; l++) {
        // norm = rmsnorm(res) * w
        rmsnorm_kernel<<<MROWS/8, 256>>>(norm_w + (size_t)l*DM);

        // xz = norm @ in_w^T   (3072 x 1024 x 256)
        {
            dim3 grid((2*DI)/128, MROWS/128);
            sgemm_nt<128,128><<<grid, 256>>>(p_norm, in_w + (size_t)l*2*DI*DM,
                                             p_xz, MROWS, 2*DI, DM);
        }

        // fused conv+silu+x_proj: writes g_xc and g_xdbl
        xproj_conv_kernel<<<MROWS/16, 256>>>(x_w + (size_t)l*48*DI,
                                             conv_w + (size_t)l*DI*4,
                                             conv_b + (size_t)l*DI);

        // scan: S1 (P,Q,dt,e1), hin (chunk-prefix), S2 (rescan + gate)
        scan_s1_kernel<<<sgrid, 128>>>(Alog + (size_t)l*DI*DS,
                                       dtw  + (size_t)l*DI*DTR,
                                       dtb  + (size_t)l*DI);
        hin_kernel<<<(BB*DI*DS)/256, 256>>>();
        scan_s2_kernel<<<sgrid, 128>>>(Alog + (size_t)l*DI*DS,
                                       Dsk  + (size_t)l*DI);

        // res += y @ out_w^T   (residual update fused into epilogue)
        {
            dim3 grid(DM/64, MROWS/64);
            outproj_gemm<<<grid, 256>>>(p_y, out_w + (size_t)l*DM*DI);
        }
    }

    final_kernel<<<MROWS, DM>>>(norm_f, ln_w, ln_b, out);
}

// round 16
// speedup vs baseline: 1.0904x; 1.0031x over previous
#include <cuda_runtime.h>
#include <cuda_bf16.h>
#include <cstdint>

// Problem constants
#define BB   4
#define NN   1024
#define DM   256
#define LL   768          // MAX_VIS
#define DI   512          // D_INNER
#define DS   16           // D_STATE
#define DTR  16           // DT_RANK
#define MROWS (BB*LL)     // 3072
#define DEPTH 12
#define TCH  48           // scan chunk length
#define KCH  16           // chunks (TCH*KCH == LL)

// ---------------- scratch (device globals; no allocation allowed) ----------
__device__ __align__(16) float g_res [MROWS*DM];   // running residual
__device__ __align__(16) float g_norm[MROWS*DM];
__device__ __align__(16) float g_xz  [MROWS*2*DI];
__device__ __align__(16) float g_xc  [MROWS*DI];
__device__ __align__(16) float g_xdbl[MROWS*48];
__device__ __align__(16) float4 g_pack[MROWS*DI];  // (dt, xv, e1, zv)
__device__ __align__(16) float g_pq  [BB*DI*KCH*32];
__device__ __align__(16) float g_hin [BB*KCH*DI*DS];
__device__ __align__(16) float g_y   [MROWS*DI];
__device__ int   g_src[BB*LL];
__device__ int   g_maskflag;
__device__ int   g_afast;

// ---------------- helpers ---------------------------------------------------
__device__ __forceinline__ float block_sum_256(float v) {
    __shared__ float sh[8];
    __syncthreads();
#pragma unroll
    for (int o = 16; o; o >>= 1) v += __shfl_xor_sync(0xffffffffu, v, o);
    if ((threadIdx.x & 31) == 0) sh[threadIdx.x >> 5] = v;
    __syncthreads();
    float t = 0.f;
#pragma unroll
    for (int i = 0; i < 8; i++) t += sh[i];
    return t;
}

__device__ __forceinline__ float silu_fast(float x) { return x / (1.f + __expf(-x)); }

// binary-power table dA[s] = e1^(s+1), s=0..15
__device__ __forceinline__ void pow_table(float e1, float* dA) {
    float e2 = e1*e1, e4 = e2*e2, e8 = e4*e4;
    dA[0]=e1;        dA[1]=e2;       dA[2]=e2*e1;     dA[3]=e4;
    dA[4]=e4*e1;     dA[5]=e4*e2;    dA[6]=dA[5]*e1;  dA[7]=e8;
    dA[8]=e8*e1;     dA[9]=e8*e2;    dA[10]=dA[9]*e1; dA[11]=e8*e4;
    dA[12]=dA[11]*e1; dA[13]=dA[11]*e2; dA[14]=dA[13]*e1; dA[15]=e8*e8;
}

// ---------------- mask dtype detection + flags init -------------------------
__global__ void detect_mask_kernel(const unsigned char* __restrict__ m) {
    int lane = threadIdx.x;
    int s = 0;
    for (int i = lane; i < 4096; i += 32) s += m[i];
#pragma unroll
    for (int o = 16; o; o >>= 1) s += __shfl_xor_sync(0xffffffffu, s, o);
    if (lane == 0) {
        int f;
        if (s == 256)        f = 1;   // int32
        else if (s == 48896) f = 2;   // float32
        else                 f = 0;   // bytes
        g_maskflag = f;
        g_afast = 1;
    }
}

// ---------------- A-structure check: A_s == (s+1)*A_1 ? ---------------------
__global__ void check_A_kernel(const float* __restrict__ Alog, int n) {
    int i = blockIdx.x * blockDim.x + threadIdx.x;
    if (i >= n) return;
    int s = i & 15;
    float A1 = expf(Alog[i - s]);
    float As = expf(Alog[i]);
    if (fabsf(As - (float)(s+1)*A1) > 1e-4f * fabsf(As))
        atomicExch(&g_afast, 0);
}

// ---------------- gather index build (stable compaction order) --------------
__global__ void gather_idx_kernel(const void* __restrict__ maskraw) {
    __shared__ int sscan[NN];
    int b = blockIdx.x, t = threadIdx.x;
    int flag = g_maskflag;
    int mv;
    if (flag == 1)      mv = ((const int*)maskraw)[b*NN + t] != 0;
    else if (flag == 2) mv = ((const float*)maskraw)[b*NN + t] != 0.f;
    else                mv = ((const unsigned char*)maskraw)[b*NN + t] != 0;
    int keep = !mv;
    sscan[t] = keep;
    __syncthreads();
    for (int off = 1; off < NN; off <<= 1) {
        int v = sscan[t];
        if (t >= off) v += sscan[t - off];
        __syncthreads();
        sscan[t] = v;
        __syncthreads();
    }
    if (keep) {
        int pos = sscan[t] - 1;
        if (pos < LL) g_src[b*LL + pos] = t;
    }
}

// ---------------- gather copy: residual_0 = visible tokens ------------------
__global__ void gather_copy_kernel(const float* __restrict__ tokens) {
    int row = blockIdx.x;
    int b = row / LL;
    int src = g_src[row];
    int c = threadIdx.x;
    g_res[(size_t)row*DM + c] = tokens[((size_t)b*NN + src)*DM + c];
}

// ---------------- rmsnorm (warp per row): norm = rmsnorm(res)*w --------------
__global__ __launch_bounds__(256)
void rmsnorm_kernel(const float* __restrict__ w) {
    const int warp = threadIdx.x >> 5, lane = threadIdx.x & 31;
    const int row = blockIdx.x * 8 + warp;
    const size_t base = (size_t)row*DM + lane*8;
    float4 r0 = *(const float4*)&g_res[base];
    float4 r1 = *(const float4*)&g_res[base+4];
    float ss = r0.x*r0.x + r0.y*r0.y + r0.z*r0.z + r0.w*r0.w
             + r1.x*r1.x + r1.y*r1.y + r1.z*r1.z + r1.w*r1.w;
#pragma unroll
    for (int o = 16; o; o >>= 1) ss += __shfl_xor_sync(0xffffffffu, ss, o);
    float rs = rsqrtf(ss * (1.f/DM) + 1e-5f);
    float4 w0 = __ldg((const float4*)&w[lane*8]);
    float4 w1 = __ldg((const float4*)&w[lane*8+4]);
    float4 o0 = make_float4(r0.x*rs*w0.x, r0.y*rs*w0.y, r0.z*rs*w0.z, r0.w*rs*w0.w);
    float4 o1 = make_float4(r1.x*rs*w1.x, r1.y*rs*w1.y, r1.z*rs*w1.z, r1.w*rs*w1.w);
    *(float4*)&g_norm[base]   = o0;
    *(float4*)&g_norm[base+4] = o1;
}

// ---------------- double-buffered SGEMM: C[M,N] = A[M,K] * B[N,K]^T ---------
template<int BM, int BN>
__global__ __launch_bounds__(256, 2)
void sgemm_nt(const float* __restrict__ A, const float* __restrict__ B,
              float* __restrict__ C, int M, int N, int K) {
    constexpr int RC = BM / 64;
    constexpr int CC = BN / 64;
    __shared__ float As[2][8][BM];
    __shared__ float Bs[2][8][BN];
    const int tid = threadIdx.x;
    const int tx = tid & 15, ty = tid >> 4;
    const int m0 = blockIdx.y * BM, n0 = blockIdx.x * BN;

    float acc[RC*4][CC*4];
#pragma unroll
    for (int i = 0; i < RC*4; i++)
#pragma unroll
        for (int j = 0; j < CC*4; j++) acc[i][j] = 0.f;

    const bool hasA = tid < BM*2;
    const bool hasB = tid < BN*2;
    const int arow = tid >> 1, akc = (tid & 1) * 4;

    if (hasA) {
        float4 v = *(const float4*)&A[(size_t)(m0+arow)*K + akc];
        As[0][akc+0][arow]=v.x; As[0][akc+1][arow]=v.y;
        As[0][akc+2][arow]=v.z; As[0][akc+3][arow]=v.w;
    }
    if (hasB) {
        float4 v = *(const float4*)&B[(size_t)(n0+arow)*K + akc];
        Bs[0][akc+0][arow]=v.x; Bs[0][akc+1][arow]=v.y;
        Bs[0][akc+2][arow]=v.z; Bs[0][akc+3][arow]=v.w;
    }
    __syncthreads();

    const int nkt = K >> 3;
    int buf = 0;
    for (int kt = 0; kt < nkt; kt++) {
        float4 va, vb;
        const bool more = (kt + 1) < nkt;
        if (more) {
            int k0n = (kt + 1) << 3;
            if (hasA) va = *(const float4*)&A[(size_t)(m0+arow)*K + k0n + akc];
            if (hasB) vb = *(const float4*)&B[(size_t)(n0+arow)*K + k0n + akc];
        }
#pragma unroll
        for (int k = 0; k < 8; k++) {
            float4 a4[RC], b4[CC];
#pragma unroll
            for (int rc = 0; rc < RC; rc++)
                a4[rc] = *(const float4*)&As[buf][k][rc*64 + ty*4];
#pragma unroll
            for (int cc = 0; cc < CC; cc++)
                b4[cc] = *(const float4*)&Bs[buf][k][cc*64 + tx*4];
#pragma unroll
            for (int rc = 0; rc < RC; rc++) {
                const float ar[4] = {a4[rc].x, a4[rc].y, a4[rc].z, a4[rc].w};
#pragma unroll
                for (int i = 0; i < 4; i++)
#pragma unroll
                    for (int cc = 0; cc < CC; cc++) {
                        acc[rc*4+i][cc*4+0] += ar[i] * b4[cc].x;
                        acc[rc*4+i][cc*4+1] += ar[i] * b4[cc].y;
                        acc[rc*4+i][cc*4+2] += ar[i] * b4[cc].z;
                        acc[rc*4+i][cc*4+3] += ar[i] * b4[cc].w;
                    }
            }
        }
        if (more) {
            int nb = buf ^ 1;
            if (hasA) {
                As[nb][akc+0][arow]=va.x; As[nb][akc+1][arow]=va.y;
                As[nb][akc+2][arow]=va.z; As[nb][akc+3][arow]=va.w;
            }
            if (hasB) {
                Bs[nb][akc+0][arow]=vb.x; Bs[nb][akc+1][arow]=vb.y;
                Bs[nb][akc+2][arow]=vb.z; Bs[nb][akc+3][arow]=vb.w;
            }
            __syncthreads();
            buf = nb;
        }
    }

#pragma unroll
    for (int rc = 0; rc < RC; rc++)
#pragma unroll
        for (int i = 0; i < 4; i++) {
            int m = m0 + rc*64 + ty*4 + i;
#pragma unroll
            for (int cc = 0; cc < CC; cc++) {
                float4 o = make_float4(acc[rc*4+i][cc*4+0], acc[rc*4+i][cc*4+1],
                                       acc[rc*4+i][cc*4+2], acc[rc*4+i][cc*4+3]);
                *(float4*)&C[(size_t)m*N + n0 + cc*64 + tx*4] = o;
            }
        }
}

// ---------------- out_proj GEMM: g_res += g_y @ out_w^T ----------------------
__global__ __launch_bounds__(256, 2)
void outproj_gemm(const float* __restrict__ A, const float* __restrict__ B) {
    constexpr int BM = 64, BN = 64, Kk = DI, Nn = DM;
    __shared__ float As[2][8][BM];
    __shared__ float Bs[2][8][BN];
    const int tid = threadIdx.x;
    const int tx = tid & 15, ty = tid >> 4;
    const int m0 = blockIdx.y * BM, n0 = blockIdx.x * BN;

    float acc[4][4];
#pragma unroll
    for (int i = 0; i < 4; i++)
#pragma unroll
        for (int j = 0; j < 4; j++) acc[i][j] = 0.f;

    const bool hasL = tid < BM*2;   // 128 loader threads
    const int arow = tid >> 1, akc = (tid & 1) * 4;

    if (hasL) {
        float4 v = *(const float4*)&A[(size_t)(m0+arow)*Kk + akc];
        As[0][akc+0][arow]=v.x; As[0][akc+1][arow]=v.y;
        As[0][akc+2][arow]=v.z; As[0][akc+3][arow]=v.w;
        float4 b = *(const float4*)&B[(size_t)(n0+arow)*Kk + akc];
        Bs[0][akc+0][arow]=b.x; Bs[0][akc+1][arow]=b.y;
        Bs[0][akc+2][arow]=b.z; Bs[0][akc+3][arow]=b.w;
    }
    __syncthreads();

    const int nkt = Kk >> 3;
    int buf = 0;
    for (int kt = 0; kt < nkt; kt++) {
        float4 va, vb;
        const bool more = (kt + 1) < nkt;
        if (more && hasL) {
            int k0n = (kt + 1) << 3;
            va = *(const float4*)&A[(size_t)(m0+arow)*Kk + k0n + akc];
            vb = *(const float4*)&B[(size_t)(n0+arow)*Kk + k0n + akc];
        }
#pragma unroll
        for (int k = 0; k < 8; k++) {
            float4 a4 = *(const float4*)&As[buf][k][ty*4];
            float4 b4 = *(const float4*)&Bs[buf][k][tx*4];
            const float ar[4] = {a4.x, a4.y, a4.z, a4.w};
#pragma unroll
            for (int i = 0; i < 4; i++) {
                acc[i][0] += ar[i] * b4.x;
                acc[i][1] += ar[i] * b4.y;
                acc[i][2] += ar[i] * b4.z;
                acc[i][3] += ar[i] * b4.w;
            }
        }
        if (more) {
            int nb = buf ^ 1;
            if (hasL) {
                As[nb][akc+0][arow]=va.x; As[nb][akc+1][arow]=va.y;
                As[nb][akc+2][arow]=va.z; As[nb][akc+3][arow]=va.w;
                Bs[nb][akc+0][arow]=vb.x; Bs[nb][akc+1][arow]=vb.y;
                Bs[nb][akc+2][arow]=vb.z; Bs[nb][akc+3][arow]=vb.w;
            }
            __syncthreads();
            buf = nb;
        }
    }

#pragma unroll
    for (int i = 0; i < 4; i++) {
        int m = m0 + ty*4 + i;
        float* cp = &g_res[(size_t)m*Nn + n0 + tx*4];
        float4 old = *(const float4*)cp;
        old.x += acc[i][0]; old.y += acc[i][1];
        old.z += acc[i][2]; old.w += acc[i][3];
        *(float4*)cp = old;
    }
}

// ---------------- fused conv+silu+x_proj -------------------------------------
__global__ __launch_bounds__(256)
void xproj_conv_kernel(const float* __restrict__ xw,
                       const float* __restrict__ cw,
                       const float* __restrict__ cb) {
    __shared__ float As[16][129];
    __shared__ float Bs[48][129];
    const int tid = threadIdx.x;
    const int m0 = blockIdx.x * 16;
    const int row = tid >> 4, col0 = tid & 15;
    float acc0 = 0.f, acc1 = 0.f, acc2 = 0.f;
    for (int kc = 0; kc < DI; kc += 128) {
#pragma unroll
        for (int i = tid; i < 16*32; i += 256) {
            int r = i >> 5, cj = (i & 31) << 2;
            int d = kc + cj;
            int m = m0 + r;
            int t = m % LL;
            const float* xzp = g_xz + (size_t)m*(2*DI) + d;
            float4 x0 = *(const float4*)xzp;
            float4 x1 = make_float4(0,0,0,0), x2 = x1, x3 = x1;
            if (t >= 1) x1 = *(const float4*)(xzp -   2*DI);
            if (t >= 2) x2 = *(const float4*)(xzp - 2*2*DI);
            if (t >= 3) x3 = *(const float4*)(xzp - 3*2*DI);
            float4 cw0 = *(const float4*)&cw[(d+0)*4];
            float4 cw1 = *(const float4*)&cw[(d+1)*4];
            float4 cw2 = *(const float4*)&cw[(d+2)*4];
            float4 cw3 = *(const float4*)&cw[(d+3)*4];
            float4 cbv = *(const float4*)&cb[d];
            float4 o;
            o.x = cbv.x + cw0.w*x0.x + cw0.z*x1.x + cw0.y*x2.x + cw0.x*x3.x;
            o.y = cbv.y + cw1.w*x0.y + cw1.z*x1.y + cw1.y*x2.y + cw1.x*x3.y;
            o.z = cbv.z + cw2.w*x0.z + cw2.z*x1.z + cw2.y*x2.z + cw2.x*x3.z;
            o.w = cbv.w + cw3.w*x0.w + cw3.z*x1.w + cw3.y*x2.w + cw3.x*x3.w;
            o.x = silu_fast(o.x); o.y = silu_fast(o.y);
            o.z = silu_fast(o.z); o.w = silu_fast(o.w);
            As[r][cj]=o.x; As[r][cj+1]=o.y; As[r][cj+2]=o.z; As[r][cj+3]=o.w;
            *(float4*)&g_xc[(size_t)m*DI + d] = o;
        }
#pragma unroll
        for (int i = tid; i < 48*32; i += 256) {
            int r = i >> 5, c4 = (i & 31) << 2;
            float4 v = *(const float4*)&xw[(size_t)r*DI + kc + c4];
            Bs[r][c4]=v.x; Bs[r][c4+1]=v.y; Bs[r][c4+2]=v.z; Bs[r][c4+3]=v.w;
        }
        __syncthreads();
#pragma unroll 4
        for (int k = 0; k < 128; k++) {
            float a = As[row][k];
            acc0 += a * Bs[col0][k];
            acc1 += a * Bs[col0+16][k];
            acc2 += a * Bs[col0+32][k];
        }
        __syncthreads();
    }
    float* o = &g_xdbl[(size_t)(m0+row)*48];
    o[col0]      = acc0;
    o[col0+16]   = acc1;
    o[col0+32]   = acc2;
}

// ---------------- scan S1: per-chunk (P,Q) + packed (dt,xv,e1,zv) ------------
__global__ __launch_bounds__(128)
void scan_s1_kernel(const float* __restrict__ Alog,
                    const float* __restrict__ dtw,
                    const float* __restrict__ dtb) {
    __shared__ __align__(16) float srow[TCH][32];   // [t][0:16)=dtr, [16:32)=B
    const int tid = threadIdx.x;
    const int d = blockIdx.x * 128 + tid;
    const int c = blockIdx.y;
    const int b = blockIdx.z;
    const int t0 = c * TCH;
    const int fast = g_afast;

    for (int i = tid; i < TCH*32; i += 128) {
        int t = i >> 5, j = i & 31;
        srow[t][j] = g_xdbl[((size_t)(b*LL + t0 + t))*48 + j];
    }

    float4 w0 = __ldg((const float4*)&dtw[d*DTR +  0]);
    float4 w1 = __ldg((const float4*)&dtw[d*DTR +  4]);
    float4 w2 = __ldg((const float4*)&dtw[d*DTR +  8]);
    float4 w3 = __ldg((const float4*)&dtw[d*DTR + 12]);
    const float bias = __ldg(&dtb[d]);
    const float A1 = -__expf(__ldg(&Alog[d*DS]));

    float Av[DS];
    if (!fast) {
#pragma unroll
        for (int s = 0; s < DS; s++) Av[s] = -__expf(__ldg(&Alog[d*DS + s]));
    }

    const float* xcp = g_xc + (size_t)(b*LL + t0)*DI + d;
    const float* zp  = g_xz + (size_t)(b*LL + t0)*(2*DI) + DI + d;

    float P[DS], Q[DS];
#pragma unroll
    for (int s = 0; s < DS; s++) { P[s] = 1.f; Q[s] = 0.f; }
    float E = 1.f;

    __syncthreads();

    float xb[2][4], zb[2][4];
#pragma unroll
    for (int k = 0; k < 4; k++) {
        xb[0][k] = xcp[(size_t)k*DI];
        zb[0][k] = zp [(size_t)k*2*DI];
    }

    const int NG = TCH/4;
    for (int g = 0; g < NG; g++) {
        const int pb = g & 1;
        if (g + 1 < NG) {
#pragma unroll
            for (int k = 0; k < 4; k++) {
                xb[pb^1][k] = xcp[(size_t)((g+1)*4 + k)*DI];
                zb[pb^1][k] = zp [(size_t)((g+1)*4 + k)*2*DI];
            }
        }
#pragma unroll
        for (int k = 0; k < 4; k++) {
            const int t = g*4 + k;
            float4 r0 = *(const float4*)&srow[t][0];
            float4 r1 = *(const float4*)&srow[t][4];
            float4 r2 = *(const float4*)&srow[t][8];
            float4 r3 = *(const float4*)&srow[t][12];
            float v = bias
                + r0.x*w0.x + r0.y*w0.y + r0.z*w0.z + r0.w*w0.w
                + r1.x*w1.x + r1.y*w1.y + r1.z*w1.z + r1.w*w1.w
                + r2.x*w2.x + r2.y*w2.y + r2.z*w2.z + r2.w*w2.w
                + r3.x*w3.x + r3.y*w3.y + r3.z*w3.z + r3.w*w3.w;
            float dt = fmaxf(v, 0.f) + __logf(1.f + __expf(-fabsf(v)));
            size_t idx = (size_t)(b*LL + t0 + t)*DI + d;
            float xv = xb[pb][k];
            float cdt = dt * xv;
            float e1 = __expf(dt * A1);
            g_pack[idx] = make_float4(dt, xv, e1, zb[pb][k]);

            float4 b0 = *(const float4*)&srow[t][16];
            float4 b1 = *(const float4*)&srow[t][20];
            float4 b2 = *(const float4*)&srow[t][24];
            float4 b3 = *(const float4*)&srow[t][28];
            float Bv[DS] = {b0.x,b0.y,b0.z,b0.w, b1.x,b1.y,b1.z,b1.w,
                            b2.x,b2.y,b2.z,b2.w, b3.x,b3.y,b3.z,b3.w};

            if (fast) {
                float dA[DS];
                pow_table(e1, dA);
                E *= e1;
#pragma unroll
                for (int s = 0; s < DS; s++) Q[s] = dA[s]*Q[s] + cdt*Bv[s];
            } else {
#pragma unroll
                for (int s = 0; s < DS; s++) {
                    float dA = __expf(dt * Av[s]);
                    P[s] *= dA;
                    Q[s] = dA*Q[s] + cdt*Bv[s];
                }
            }
        }
    }
    if (fast) pow_table(E, P);

    float* pq = g_pq + ((size_t)(b*DI + d)*KCH + c)*32;
#pragma unroll
    for (int s = 0; s < DS; s += 4)
        *(float4*)&pq[s] = make_float4(P[s],P[s+1],P[s+2],P[s+3]);
#pragma unroll
    for (int s = 0; s < DS; s += 4)
        *(float4*)&pq[16+s] = make_float4(Q[s],Q[s+1],Q[s+2],Q[s+3]);
}

// ---------------- hin: chunk-prefix scan over (P,Q) --------------------------
__global__ __launch_bounds__(256)
void hin_kernel() {
    const int g = blockIdx.x * 256 + threadIdx.x;   // 0..BB*DI*DS-1
    const int s = g & 15;
    const int d = (g >> 4) & (DI-1);
    const int b = g >> 13;
    const float* pqb = g_pq + ((size_t)(b*DI + d)*KCH)*32;
    float h = 0.f;
#pragma unroll
    for (int cc = 0; cc < KCH; cc++) {
        g_hin[((size_t)(b*KCH + cc)*DI + d)*DS + s] = h;
        float P = pqb[cc*32 + s];
        float Q = pqb[cc*32 + 16 + s];
        h = P*h + Q;
    }
}

// ---------------- scan S2: load h_in, rescan chunk, emit y -------------------
__global__ __launch_bounds__(128)
void scan_s2_kernel(const float* __restrict__ Alog,
                    const float* __restrict__ Dsk) {
    __shared__ __align__(16) float srow[TCH][32];   // [t][0:16)=B, [16:32)=C
    const int tid = threadIdx.x;
    const int d = blockIdx.x * 128 + tid;
    const int c = blockIdx.y;
    const int b = blockIdx.z;
    const int t0 = c * TCH;
    const int fast = g_afast;
    const float Dd = __ldg(&Dsk[d]);

    for (int i = tid; i < TCH*32; i += 128) {
        int t = i >> 5, j = i & 31;
        srow[t][j] = g_xdbl[((size_t)(b*LL + t0 + t))*48 + 16 + j];
    }

    float Av[DS];
    if (!fast) {
#pragma unroll
        for (int s = 0; s < DS; s++) Av[s] = -__expf(__ldg(&Alog[d*DS + s]));
    }

    float h[DS];
    {
        const float* hp = g_hin + ((size_t)(b*KCH + c)*DI + d)*DS;
#pragma unroll
        for (int s = 0; s < DS; s += 4) {
            float4 v = *(const float4*)&hp[s];
            h[s]=v.x; h[s+1]=v.y; h[s+2]=v.z; h[s+3]=v.w;
        }
    }

    const size_t sbase = (size_t)(b*LL + t0)*DI + d;
    const float4* pkp = g_pack + sbase;
    float*        yp  = g_y    + sbase;

    __syncthreads();

    // group-prefetched packed stream (groups of 4 t-steps, double buffered)
    float4 pk[2][4];
#pragma unroll
    for (int k = 0; k < 4; k++) pk[0][k] = pkp[(size_t)k*DI];

    const int NG = TCH/4;
    for (int g = 0; g < NG; g++) {
        const int pb = g & 1;
        if (g + 1 < NG) {
#pragma unroll
            for (int k = 0; k < 4; k++)
                pk[pb^1][k] = pkp[(size_t)((g+1)*4 + k)*DI];
        }
#pragma unroll
        for (int k = 0; k < 4; k++) {
            const int t = g*4 + k;
            float dt = pk[pb][k].x;
            float xv = pk[pb][k].y;
            float e1 = pk[pb][k].z;
            float zv = pk[pb][k].w;
            float cdt = dt * xv;

            float4 b0 = *(const float4*)&srow[t][0];
            float4 b1 = *(const float4*)&srow[t][4];
            float4 b2 = *(const float4*)&srow[t][8];
            float4 b3 = *(const float4*)&srow[t][12];
            float4 c0 = *(const float4*)&srow[t][16];
            float4 c1 = *(const float4*)&srow[t][20];
            float4 c2 = *(const float4*)&srow[t][24];
            float4 c3 = *(const float4*)&srow[t][28];
            float Bv[DS] = {b0.x,b0.y,b0.z,b0.w, b1.x,b1.y,b1.z,b1.w,
                            b2.x,b2.y,b2.z,b2.w, b3.x,b3.y,b3.z,b3.w};
            float Cv[DS] = {c0.x,c0.y,c0.z,c0.w, c1.x,c1.y,c1.z,c1.w,
                            c2.x,c2.y,c2.z,c2.w, c3.x,c3.y,c3.z,c3.w};

            float dA[DS];
            if (fast) {
                pow_table(e1, dA);
            } else {
#pragma unroll
                for (int s = 0; s < DS; s++) dA[s] = __expf(dt * Av[s]);
            }
            float p = 0.f;
#pragma unroll
            for (int s = 0; s < DS; s++) {
                h[s] = dA[s]*h[s] + cdt*Bv[s];
                p += h[s]*Cv[s];
            }
            yp[(size_t)t*DI] = (p + Dd*xv) * silu_fast(zv);
        }
    }
}

// ---------------- final: rmsnorm + layernorm + output layout ----------------
__global__ void final_kernel(const float* __restrict__ wf,
                             const float* __restrict__ lw,
                             const float* __restrict__ lb,
                             float* __restrict__ out) {
    int row = blockIdx.x, c = threadIdx.x;
    size_t idx = (size_t)row*DM + c;
    float h = g_res[idx];           // residual already includes final hidden
    float ss = block_sum_256(h*h);
    h = h * rsqrtf(ss * (1.f/DM) + 1e-5f) * wf[c];
    float mu = block_sum_256(h) * (1.f/DM);
    float hm = h - mu;
    float var = block_sum_256(hm*hm) * (1.f/DM);
    float o = hm * rsqrtf(var + 1e-5f) * lw[c] + lb[c];
    int b = row / LL, t = row % LL;
    size_t dst = (t < LL-1) ? ((size_t)(b*(LL-1) + t)*DM + c)
                            : ((size_t)BB*(LL-1)*DM + (size_t)b*DM + c);
    out[dst] = o;
}

// ---------------- host launch -----------------------------------------------
static float* sym_addr(const void* sym) {
    void* p = nullptr;
    cudaGetSymbolAddress(&p, sym);
    return (float*)p;
}

extern "C" void kernel_launch(void* const* d_in, const int* in_sizes, int n_in,
                              void* d_out, int out_size) {
    const float* tokens = (const float*)d_in[0];
    const void*  mask   = d_in[1];
    const float* in_w   = (const float*)d_in[2];
    const float* conv_w = (const float*)d_in[3];
    const float* conv_b = (const float*)d_in[4];
    const float* x_w    = (const float*)d_in[5];
    const float* dtw    = (const float*)d_in[6];
    const float* dtb    = (const float*)d_in[7];
    const float* Alog   = (const float*)d_in[8];
    const float* Dsk    = (const float*)d_in[9];
    const float* out_w  = (const float*)d_in[10];
    const float* norm_w = (const float*)d_in[11];
    const float* norm_f = (const float*)d_in[12];
    const float* ln_w   = (const float*)d_in[13];
    const float* ln_b   = (const float*)d_in[14];
    float* out = (float*)d_out;

    float* p_norm = sym_addr(g_norm);
    float* p_xz   = sym_addr(g_xz);
    float* p_y    = sym_addr(g_y);

    detect_mask_kernel<<<1, 32>>>((const unsigned char*)mask);
    {
        int n = DEPTH*DI*DS;
        check_A_kernel<<<(n + 255)/256, 256>>>(Alog, n);
    }
    gather_idx_kernel<<<BB, NN>>>(mask);
    gather_copy_kernel<<<MROWS, DM>>>(tokens);

    dim3 sgrid(DI/128, KCH, BB);

    for (int l = 0; l < DEPTH; l++) {
        // norm = rmsnorm(res) * w
        rmsnorm_kernel<<<MROWS/8, 256>>>(norm_w + (size_t)l*DM);

        // xz = norm @ in_w^T   (3072 x 1024 x 256)
        {
            dim3 grid((2*DI)/128, MROWS/128);
            sgemm_nt<128,128><<<grid, 256>>>(p_norm, in_w + (size_t)l*2*DI*DM,
                                             p_xz, MROWS, 2*DI, DM);
        }

        // fused conv+silu+x_proj: writes g_xc and g_xdbl
        xproj_conv_kernel<<<MROWS/16, 256>>>(x_w + (size_t)l*48*DI,
                                             conv_w + (size_t)l*DI*4,
                                             conv_b + (size_t)l*DI);

        // scan: S1 (P,Q + packed stream), hin (chunk-prefix), S2 (rescan+gate)
        scan_s1_kernel<<<sgrid, 128>>>(Alog + (size_t)l*DI*DS,
                                       dtw  + (size_t)l*DI*DTR,
                                       dtb  + (size_t)l*DI);
        hin_kernel<<<(BB*DI*DS)/256, 256>>>();
        scan_s2_kernel<<<sgrid, 128>>>(Alog + (size_t)l*DI*DS,
                                       Dsk  + (size_t)l*DI);

        // res += y @ out_w^T   (residual update fused into epilogue)
        {
            dim3 grid(DM/64, MROWS/64);
            outproj_gemm<<<grid, 256>>>(p_y, out_w + (size_t)l*DM*DI);
        }
    }

    final_kernel<<<MROWS, DM>>>(norm_f, ln_w, ln_b, out);
}

// round 17
// speedup vs baseline: 1.1088x; 1.0168x over previous
#include <cuda_runtime.h>
#include <cuda_bf16.h>
#include <cstdint>

// Problem constants
#define BB   4
#define NN   1024
#define DM   256
#define LL   768          // MAX_VIS
#define DI   512          // D_INNER
#define DS   16           // D_STATE
#define DTR  16           // DT_RANK
#define MROWS (BB*LL)     // 3072
#define DEPTH 12
#define TCH  48           // scan chunk length
#define KCH  16           // chunks (TCH*KCH == LL)

// ---------------- scratch (device globals; no allocation allowed) ----------
__device__ __align__(16) float g_res [MROWS*DM];   // running residual
__device__ __align__(16) float g_norm[MROWS*DM];
__device__ __align__(16) float g_xz  [MROWS*2*DI];
__device__ __align__(16) float g_xc  [MROWS*DI];
__device__ __align__(16) float g_xdbl[MROWS*48];
__device__ __align__(16) float4 g_pack[MROWS*DI];  // (dt, xv, e1, zv)
__device__ __align__(16) float g_pq  [BB*DI*KCH*32];
__device__ __align__(16) float g_hin [BB*KCH*DI*DS];
__device__ __align__(16) float g_y   [MROWS*DI];
__device__ int   g_src[BB*LL];
__device__ int   g_maskflag;
__device__ int   g_afast;

// ---------------- helpers ---------------------------------------------------
__device__ __forceinline__ float block_sum_256(float v) {
    __shared__ float sh[8];
    __syncthreads();
#pragma unroll
    for (int o = 16; o; o >>= 1) v += __shfl_xor_sync(0xffffffffu, v, o);
    if ((threadIdx.x & 31) == 0) sh[threadIdx.x >> 5] = v;
    __syncthreads();
    float t = 0.f;
#pragma unroll
    for (int i = 0; i < 8; i++) t += sh[i];
    return t;
}

__device__ __forceinline__ float silu_fast(float x) { return x / (1.f + __expf(-x)); }

// binary-power table dA[s] = e1^(s+1), s=0..15
__device__ __forceinline__ void pow_table(float e1, float* dA) {
    float e2 = e1*e1, e4 = e2*e2, e8 = e4*e4;
    dA[0]=e1;        dA[1]=e2;       dA[2]=e2*e1;     dA[3]=e4;
    dA[4]=e4*e1;     dA[5]=e4*e2;    dA[6]=dA[5]*e1;  dA[7]=e8;
    dA[8]=e8*e1;     dA[9]=e8*e2;    dA[10]=dA[9]*e1; dA[11]=e8*e4;
    dA[12]=dA[11]*e1; dA[13]=dA[11]*e2; dA[14]=dA[13]*e1; dA[15]=e8*e8;
}

// ---------------- mask dtype detection + flags init -------------------------
__global__ void detect_mask_kernel(const unsigned char* __restrict__ m) {
    int lane = threadIdx.x;
    int s = 0;
    for (int i = lane; i < 4096; i += 32) s += m[i];
#pragma unroll
    for (int o = 16; o; o >>= 1) s += __shfl_xor_sync(0xffffffffu, s, o);
    if (lane == 0) {
        int f;
        if (s == 256)        f = 1;   // int32
        else if (s == 48896) f = 2;   // float32
        else                 f = 0;   // bytes
        g_maskflag = f;
        g_afast = 1;
    }
}

// ---------------- A-structure check: A_s == (s+1)*A_1 ? ---------------------
__global__ void check_A_kernel(const float* __restrict__ Alog, int n) {
    int i = blockIdx.x * blockDim.x + threadIdx.x;
    if (i >= n) return;
    int s = i & 15;
    float A1 = expf(Alog[i - s]);
    float As = expf(Alog[i]);
    if (fabsf(As - (float)(s+1)*A1) > 1e-4f * fabsf(As))
        atomicExch(&g_afast, 0);
}

// ---------------- gather index build (stable compaction order) --------------
__global__ void gather_idx_kernel(const void* __restrict__ maskraw) {
    __shared__ int sscan[NN];
    int b = blockIdx.x, t = threadIdx.x;
    int flag = g_maskflag;
    int mv;
    if (flag == 1)      mv = ((const int*)maskraw)[b*NN + t] != 0;
    else if (flag == 2) mv = ((const float*)maskraw)[b*NN + t] != 0.f;
    else                mv = ((const unsigned char*)maskraw)[b*NN + t] != 0;
    int keep = !mv;
    sscan[t] = keep;
    __syncthreads();
    for (int off = 1; off < NN; off <<= 1) {
        int v = sscan[t];
        if (t >= off) v += sscan[t - off];
        __syncthreads();
        sscan[t] = v;
        __syncthreads();
    }
    if (keep) {
        int pos = sscan[t] - 1;
        if (pos < LL) g_src[b*LL + pos] = t;
    }
}

// ---------------- gather copy: residual_0 = visible tokens ------------------
__global__ void gather_copy_kernel(const float* __restrict__ tokens) {
    int row = blockIdx.x;
    int b = row / LL;
    int src = g_src[row];
    int c = threadIdx.x;
    g_res[(size_t)row*DM + c] = tokens[((size_t)b*NN + src)*DM + c];
}

// ---------------- rmsnorm (warp per row): norm = rmsnorm(res)*w --------------
__global__ __launch_bounds__(256)
void rmsnorm_kernel(const float* __restrict__ w) {
    const int warp = threadIdx.x >> 5, lane = threadIdx.x & 31;
    const int row = blockIdx.x * 8 + warp;
    const size_t base = (size_t)row*DM + lane*8;
    float4 r0 = *(const float4*)&g_res[base];
    float4 r1 = *(const float4*)&g_res[base+4];
    float ss = r0.x*r0.x + r0.y*r0.y + r0.z*r0.z + r0.w*r0.w
             + r1.x*r1.x + r1.y*r1.y + r1.z*r1.z + r1.w*r1.w;
#pragma unroll
    for (int o = 16; o; o >>= 1) ss += __shfl_xor_sync(0xffffffffu, ss, o);
    float rs = rsqrtf(ss * (1.f/DM) + 1e-5f);
    float4 w0 = __ldg((const float4*)&w[lane*8]);
    float4 w1 = __ldg((const float4*)&w[lane*8+4]);
    float4 o0 = make_float4(r0.x*rs*w0.x, r0.y*rs*w0.y, r0.z*rs*w0.z, r0.w*rs*w0.w);
    float4 o1 = make_float4(r1.x*rs*w1.x, r1.y*rs*w1.y, r1.z*rs*w1.z, r1.w*rs*w1.w);
    *(float4*)&g_norm[base]   = o0;
    *(float4*)&g_norm[base+4] = o1;
}

// ---------------- double-buffered SGEMM: C[M,N] = A[M,K] * B[N,K]^T ---------
template<int BM, int BN>
__global__ __launch_bounds__(256, 2)
void sgemm_nt(const float* __restrict__ A, const float* __restrict__ B,
              float* __restrict__ C, int M, int N, int K) {
    constexpr int RC = BM / 64;
    constexpr int CC = BN / 64;
    __shared__ float As[2][8][BM];
    __shared__ float Bs[2][8][BN];
    const int tid = threadIdx.x;
    const int tx = tid & 15, ty = tid >> 4;
    const int m0 = blockIdx.y * BM, n0 = blockIdx.x * BN;

    float acc[RC*4][CC*4];
#pragma unroll
    for (int i = 0; i < RC*4; i++)
#pragma unroll
        for (int j = 0; j < CC*4; j++) acc[i][j] = 0.f;

    const bool hasA = tid < BM*2;
    const bool hasB = tid < BN*2;
    const int arow = tid >> 1, akc = (tid & 1) * 4;

    if (hasA) {
        float4 v = *(const float4*)&A[(size_t)(m0+arow)*K + akc];
        As[0][akc+0][arow]=v.x; As[0][akc+1][arow]=v.y;
        As[0][akc+2][arow]=v.z; As[0][akc+3][arow]=v.w;
    }
    if (hasB) {
        float4 v = *(const float4*)&B[(size_t)(n0+arow)*K + akc];
        Bs[0][akc+0][arow]=v.x; Bs[0][akc+1][arow]=v.y;
        Bs[0][akc+2][arow]=v.z; Bs[0][akc+3][arow]=v.w;
    }
    __syncthreads();

    const int nkt = K >> 3;
    int buf = 0;
    for (int kt = 0; kt < nkt; kt++) {
        float4 va, vb;
        const bool more = (kt + 1) < nkt;
        if (more) {
            int k0n = (kt + 1) << 3;
            if (hasA) va = *(const float4*)&A[(size_t)(m0+arow)*K + k0n + akc];
            if (hasB) vb = *(const float4*)&B[(size_t)(n0+arow)*K + k0n + akc];
        }
#pragma unroll
        for (int k = 0; k < 8; k++) {
            float4 a4[RC], b4[CC];
#pragma unroll
            for (int rc = 0; rc < RC; rc++)
                a4[rc] = *(const float4*)&As[buf][k][rc*64 + ty*4];
#pragma unroll
            for (int cc = 0; cc < CC; cc++)
                b4[cc] = *(const float4*)&Bs[buf][k][cc*64 + tx*4];
#pragma unroll
            for (int rc = 0; rc < RC; rc++) {
                const float ar[4] = {a4[rc].x, a4[rc].y, a4[rc].z, a4[rc].w};
#pragma unroll
                for (int i = 0; i < 4; i++)
#pragma unroll
                    for (int cc = 0; cc < CC; cc++) {
                        acc[rc*4+i][cc*4+0] += ar[i] * b4[cc].x;
                        acc[rc*4+i][cc*4+1] += ar[i] * b4[cc].y;
                        acc[rc*4+i][cc*4+2] += ar[i] * b4[cc].z;
                        acc[rc*4+i][cc*4+3] += ar[i] * b4[cc].w;
                    }
            }
        }
        if (more) {
            int nb = buf ^ 1;
            if (hasA) {
                As[nb][akc+0][arow]=va.x; As[nb][akc+1][arow]=va.y;
                As[nb][akc+2][arow]=va.z; As[nb][akc+3][arow]=va.w;
            }
            if (hasB) {
                Bs[nb][akc+0][arow]=vb.x; Bs[nb][akc+1][arow]=vb.y;
                Bs[nb][akc+2][arow]=vb.z; Bs[nb][akc+3][arow]=vb.w;
            }
            __syncthreads();
            buf = nb;
        }
    }

#pragma unroll
    for (int rc = 0; rc < RC; rc++)
#pragma unroll
        for (int i = 0; i < 4; i++) {
            int m = m0 + rc*64 + ty*4 + i;
#pragma unroll
            for (int cc = 0; cc < CC; cc++) {
                float4 o = make_float4(acc[rc*4+i][cc*4+0], acc[rc*4+i][cc*4+1],
                                       acc[rc*4+i][cc*4+2], acc[rc*4+i][cc*4+3]);
                *(float4*)&C[(size_t)m*N + n0 + cc*64 + tx*4] = o;
            }
        }
}

// ---------------- out_proj GEMM: g_res += g_y @ out_w^T ----------------------
__global__ __launch_bounds__(256, 2)
void outproj_gemm(const float* __restrict__ A, const float* __restrict__ B) {
    constexpr int BM = 64, BN = 64, Kk = DI, Nn = DM;
    __shared__ float As[2][8][BM];
    __shared__ float Bs[2][8][BN];
    const int tid = threadIdx.x;
    const int tx = tid & 15, ty = tid >> 4;
    const int m0 = blockIdx.y * BM, n0 = blockIdx.x * BN;

    float acc[4][4];
#pragma unroll
    for (int i = 0; i < 4; i++)
#pragma unroll
        for (int j = 0; j < 4; j++) acc[i][j] = 0.f;

    const bool hasL = tid < BM*2;   // 128 loader threads
    const int arow = tid >> 1, akc = (tid & 1) * 4;

    if (hasL) {
        float4 v = *(const float4*)&A[(size_t)(m0+arow)*Kk + akc];
        As[0][akc+0][arow]=v.x; As[0][akc+1][arow]=v.y;
        As[0][akc+2][arow]=v.z; As[0][akc+3][arow]=v.w;
        float4 b = *(const float4*)&B[(size_t)(n0+arow)*Kk + akc];
        Bs[0][akc+0][arow]=b.x; Bs[0][akc+1][arow]=b.y;
        Bs[0][akc+2][arow]=b.z; Bs[0][akc+3][arow]=b.w;
    }
    __syncthreads();

    const int nkt = Kk >> 3;
    int buf = 0;
    for (int kt = 0; kt < nkt; kt++) {
        float4 va, vb;
        const bool more = (kt + 1) < nkt;
        if (more && hasL) {
            int k0n = (kt + 1) << 3;
            va = *(const float4*)&A[(size_t)(m0+arow)*Kk + k0n + akc];
            vb = *(const float4*)&B[(size_t)(n0+arow)*Kk + k0n + akc];
        }
#pragma unroll
        for (int k = 0; k < 8; k++) {
            float4 a4 = *(const float4*)&As[buf][k][ty*4];
            float4 b4 = *(const float4*)&Bs[buf][k][tx*4];
            const float ar[4] = {a4.x, a4.y, a4.z, a4.w};
#pragma unroll
            for (int i = 0; i < 4; i++) {
                acc[i][0] += ar[i] * b4.x;
                acc[i][1] += ar[i] * b4.y;
                acc[i][2] += ar[i] * b4.z;
                acc[i][3] += ar[i] * b4.w;
            }
        }
        if (more) {
            int nb = buf ^ 1;
            if (hasL) {
                As[nb][akc+0][arow]=va.x; As[nb][akc+1][arow]=va.y;
                As[nb][akc+2][arow]=va.z; As[nb][akc+3][arow]=va.w;
                Bs[nb][akc+0][arow]=vb.x; Bs[nb][akc+1][arow]=vb.y;
                Bs[nb][akc+2][arow]=vb.z; Bs[nb][akc+3][arow]=vb.w;
            }
            __syncthreads();
            buf = nb;
        }
    }

#pragma unroll
    for (int i = 0; i < 4; i++) {
        int m = m0 + ty*4 + i;
        float* cp = &g_res[(size_t)m*Nn + n0 + tx*4];
        float4 old = *(const float4*)cp;
        old.x += acc[i][0]; old.y += acc[i][1];
        old.z += acc[i][2]; old.w += acc[i][3];
        *(float4*)cp = old;
    }
}

// ---------------- fused conv+silu+x_proj (32-row tiles, 2 rows/thread) -------
__global__ __launch_bounds__(256)
void xproj_conv_kernel(const float* __restrict__ xw,
                       const float* __restrict__ cw,
                       const float* __restrict__ cb) {
    __shared__ float As[32][129];
    __shared__ float Bs[48][129];
    const int tid = threadIdx.x;
    const int m0 = blockIdx.x * 32;
    const int row = tid >> 4, col0 = tid & 15;   // row 0..15 handles rows {row, row+16}
    float a00=0.f,a01=0.f,a02=0.f;               // row, cols col0/col0+16/col0+32
    float a10=0.f,a11=0.f,a12=0.f;               // row+16
    for (int kc = 0; kc < DI; kc += 128) {
        // A tile: conv+silu for 32 rows x 128 cols (4 iters of 256 threads x f4)
#pragma unroll
        for (int i = tid; i < 32*32; i += 256) {
            int r = i >> 5, cj = (i & 31) << 2;
            int d = kc + cj;
            int m = m0 + r;
            int t = m % LL;
            const float* xzp = g_xz + (size_t)m*(2*DI) + d;
            float4 x0 = *(const float4*)xzp;
            float4 x1 = make_float4(0,0,0,0), x2 = x1, x3 = x1;
            if (t >= 1) x1 = *(const float4*)(xzp -   2*DI);
            if (t >= 2) x2 = *(const float4*)(xzp - 2*2*DI);
            if (t >= 3) x3 = *(const float4*)(xzp - 3*2*DI);
            float4 cw0 = *(const float4*)&cw[(d+0)*4];
            float4 cw1 = *(const float4*)&cw[(d+1)*4];
            float4 cw2 = *(const float4*)&cw[(d+2)*4];
            float4 cw3 = *(const float4*)&cw[(d+3)*4];
            float4 cbv = *(const float4*)&cb[d];
            float4 o;
            o.x = cbv.x + cw0.w*x0.x + cw0.z*x1.x + cw0.y*x2.x + cw0.x*x3.x;
            o.y = cbv.y + cw1.w*x0.y + cw1.z*x1.y + cw1.y*x2.y + cw1.x*x3.y;
            o.z = cbv.z + cw2.w*x0.z + cw2.z*x1.z + cw2.y*x2.z + cw2.x*x3.z;
            o.w = cbv.w + cw3.w*x0.w + cw3.z*x1.w + cw3.y*x2.w + cw3.x*x3.w;
            o.x = silu_fast(o.x); o.y = silu_fast(o.y);
            o.z = silu_fast(o.z); o.w = silu_fast(o.w);
            As[r][cj]=o.x; As[r][cj+1]=o.y; As[r][cj+2]=o.z; As[r][cj+3]=o.w;
            *(float4*)&g_xc[(size_t)m*DI + d] = o;
        }
#pragma unroll
        for (int i = tid; i < 48*32; i += 256) {
            int r = i >> 5, c4 = (i & 31) << 2;
            float4 v = *(const float4*)&xw[(size_t)r*DI + kc + c4];
            Bs[r][c4]=v.x; Bs[r][c4+1]=v.y; Bs[r][c4+2]=v.z; Bs[r][c4+3]=v.w;
        }
        __syncthreads();
#pragma unroll 4
        for (int k = 0; k < 128; k++) {
            float a0 = As[row][k];
            float a1 = As[row+16][k];
            float b0 = Bs[col0][k];
            float b1 = Bs[col0+16][k];
            float b2 = Bs[col0+32][k];
            a00 += a0*b0; a01 += a0*b1; a02 += a0*b2;
            a10 += a1*b0; a11 += a1*b1; a12 += a1*b2;
        }
        __syncthreads();
    }
    float* o0 = &g_xdbl[(size_t)(m0+row)*48];
    o0[col0]    = a00;
    o0[col0+16] = a01;
    o0[col0+32] = a02;
    float* o1 = &g_xdbl[(size_t)(m0+row+16)*48];
    o1[col0]    = a10;
    o1[col0+16] = a11;
    o1[col0+32] = a12;
}

// ---------------- scan S1: per-chunk (P,Q) + packed (dt,xv,e1,zv) ------------
__global__ __launch_bounds__(128)
void scan_s1_kernel(const float* __restrict__ Alog,
                    const float* __restrict__ dtw,
                    const float* __restrict__ dtb) {
    __shared__ __align__(16) float srow[TCH][32];   // [t][0:16)=dtr, [16:32)=B
    const int tid = threadIdx.x;
    const int d = blockIdx.x * 128 + tid;
    const int c = blockIdx.y;
    const int b = blockIdx.z;
    const int t0 = c * TCH;
    const int fast = g_afast;

    for (int i = tid; i < TCH*32; i += 128) {
        int t = i >> 5, j = i & 31;
        srow[t][j] = g_xdbl[((size_t)(b*LL + t0 + t))*48 + j];
    }

    float4 w0 = __ldg((const float4*)&dtw[d*DTR +  0]);
    float4 w1 = __ldg((const float4*)&dtw[d*DTR +  4]);
    float4 w2 = __ldg((const float4*)&dtw[d*DTR +  8]);
    float4 w3 = __ldg((const float4*)&dtw[d*DTR + 12]);
    const float bias = __ldg(&dtb[d]);
    const float A1 = -__expf(__ldg(&Alog[d*DS]));

    float Av[DS];
    if (!fast) {
#pragma unroll
        for (int s = 0; s < DS; s++) Av[s] = -__expf(__ldg(&Alog[d*DS + s]));
    }

    const float* xcp = g_xc + (size_t)(b*LL + t0)*DI + d;
    const float* zp  = g_xz + (size_t)(b*LL + t0)*(2*DI) + DI + d;

    float P[DS], Q[DS];
#pragma unroll
    for (int s = 0; s < DS; s++) { P[s] = 1.f; Q[s] = 0.f; }
    float E = 1.f;

    __syncthreads();

    float xb[2][4], zb[2][4];
#pragma unroll
    for (int k = 0; k < 4; k++) {
        xb[0][k] = xcp[(size_t)k*DI];
        zb[0][k] = zp [(size_t)k*2*DI];
    }

    const int NG = TCH/4;
    for (int g = 0; g < NG; g++) {
        const int pb = g & 1;
        if (g + 1 < NG) {
#pragma unroll
            for (int k = 0; k < 4; k++) {
                xb[pb^1][k] = xcp[(size_t)((g+1)*4 + k)*DI];
                zb[pb^1][k] = zp [(size_t)((g+1)*4 + k)*2*DI];
            }
        }
#pragma unroll
        for (int k = 0; k < 4; k++) {
            const int t = g*4 + k;
            float4 r0 = *(const float4*)&srow[t][0];
            float4 r1 = *(const float4*)&srow[t][4];
            float4 r2 = *(const float4*)&srow[t][8];
            float4 r3 = *(const float4*)&srow[t][12];
            float v = bias
                + r0.x*w0.x + r0.y*w0.y + r0.z*w0.z + r0.w*w0.w
                + r1.x*w1.x + r1.y*w1.y + r1.z*w1.z + r1.w*w1.w
                + r2.x*w2.x + r2.y*w2.y + r2.z*w2.z + r2.w*w2.w
                + r3.x*w3.x + r3.y*w3.y + r3.z*w3.z + r3.w*w3.w;
            float dt = fmaxf(v, 0.f) + __logf(1.f + __expf(-fabsf(v)));
            size_t idx = (size_t)(b*LL + t0 + t)*DI + d;
            float xv = xb[pb][k];
            float cdt = dt * xv;
            float e1 = __expf(dt * A1);
            g_pack[idx] = make_float4(dt, xv, e1, zb[pb][k]);

            float4 b0 = *(const float4*)&srow[t][16];
            float4 b1 = *(const float4*)&srow[t][20];
            float4 b2 = *(const float4*)&srow[t][24];
            float4 b3 = *(const float4*)&srow[t][28];
            float Bv[DS] = {b0.x,b0.y,b0.z,b0.w, b1.x,b1.y,b1.z,b1.w,
                            b2.x,b2.y,b2.z,b2.w, b3.x,b3.y,b3.z,b3.w};

            if (fast) {
                float dA[DS];
                pow_table(e1, dA);
                E *= e1;
#pragma unroll
                for (int s = 0; s < DS; s++) Q[s] = dA[s]*Q[s] + cdt*Bv[s];
            } else {
#pragma unroll
                for (int s = 0; s < DS; s++) {
                    float dA = __expf(dt * Av[s]);
                    P[s] *= dA;
                    Q[s] = dA*Q[s] + cdt*Bv[s];
                }
            }
        }
    }
    if (fast) pow_table(E, P);

    float* pq = g_pq + ((size_t)(b*DI + d)*KCH + c)*32;
#pragma unroll
    for (int s = 0; s < DS; s += 4)
        *(float4*)&pq[s] = make_float4(P[s],P[s+1],P[s+2],P[s+3]);
#pragma unroll
    for (int s = 0; s < DS; s += 4)
        *(float4*)&pq[16+s] = make_float4(Q[s],Q[s+1],Q[s+2],Q[s+3]);
}

// ---------------- hin: chunk-prefix scan over (P,Q) --------------------------
__global__ __launch_bounds__(256)
void hin_kernel() {
    const int g = blockIdx.x * 256 + threadIdx.x;   // 0..BB*DI*DS-1
    const int s = g & 15;
    const int d = (g >> 4) & (DI-1);
    const int b = g >> 13;
    const float* pqb = g_pq + ((size_t)(b*DI + d)*KCH)*32;
    float h = 0.f;
#pragma unroll
    for (int cc = 0; cc < KCH; cc++) {
        g_hin[((size_t)(b*KCH + cc)*DI + d)*DS + s] = h;
        float P = pqb[cc*32 + s];
        float Q = pqb[cc*32 + 16 + s];
        h = P*h + Q;
    }
}

// ---------------- scan S2: load h_in, rescan chunk, emit y -------------------
__global__ __launch_bounds__(128)
void scan_s2_kernel(const float* __restrict__ Alog,
                    const float* __restrict__ Dsk) {
    __shared__ __align__(16) float srow[TCH][32];   // [t][0:16)=B, [16:32)=C
    const int tid = threadIdx.x;
    const int d = blockIdx.x * 128 + tid;
    const int c = blockIdx.y;
    const int b = blockIdx.z;
    const int t0 = c * TCH;
    const int fast = g_afast;
    const float Dd = __ldg(&Dsk[d]);

    for (int i = tid; i < TCH*32; i += 128) {
        int t = i >> 5, j = i & 31;
        srow[t][j] = g_xdbl[((size_t)(b*LL + t0 + t))*48 + 16 + j];
    }

    float Av[DS];
    if (!fast) {
#pragma unroll
        for (int s = 0; s < DS; s++) Av[s] = -__expf(__ldg(&Alog[d*DS + s]));
    }

    float h[DS];
    {
        const float* hp = g_hin + ((size_t)(b*KCH + c)*DI + d)*DS;
#pragma unroll
        for (int s = 0; s < DS; s += 4) {
            float4 v = *(const float4*)&hp[s];
            h[s]=v.x; h[s+1]=v.y; h[s+2]=v.z; h[s+3]=v.w;
        }
    }

    const size_t sbase = (size_t)(b*LL + t0)*DI + d;
    const float4* pkp = g_pack + sbase;
    float*        yp  = g_y    + sbase;

    __syncthreads();

    // group-prefetched packed stream (groups of 4 t-steps, double buffered)
    float4 pk[2][4];
#pragma unroll
    for (int k = 0; k < 4; k++) pk[0][k] = pkp[(size_t)k*DI];

    const int NG = TCH/4;
    for (int g = 0; g < NG; g++) {
        const int pb = g & 1;
        if (g + 1 < NG) {
#pragma unroll
            for (int k = 0; k < 4; k++)
                pk[pb^1][k] = pkp[(size_t)((g+1)*4 + k)*DI];
        }
#pragma unroll
        for (int k = 0; k < 4; k++) {
            const int t = g*4 + k;
            float dt = pk[pb][k].x;
            float xv = pk[pb][k].y;
            float e1 = pk[pb][k].z;
            float zv = pk[pb][k].w;
            float cdt = dt * xv;

            float4 b0 = *(const float4*)&srow[t][0];
            float4 b1 = *(const float4*)&srow[t][4];
            float4 b2 = *(const float4*)&srow[t][8];
            float4 b3 = *(const float4*)&srow[t][12];
            float4 c0 = *(const float4*)&srow[t][16];
            float4 c1 = *(const float4*)&srow[t][20];
            float4 c2 = *(const float4*)&srow[t][24];
            float4 c3 = *(const float4*)&srow[t][28];
            float Bv[DS] = {b0.x,b0.y,b0.z,b0.w, b1.x,b1.y,b1.z,b1.w,
                            b2.x,b2.y,b2.z,b2.w, b3.x,b3.y,b3.z,b3.w};
            float Cv[DS] = {c0.x,c0.y,c0.z,c0.w, c1.x,c1.y,c1.z,c1.w,
                            c2.x,c2.y,c2.z,c2.w, c3.x,c3.y,c3.z,c3.w};

            float dA[DS];
            if (fast) {
                pow_table(e1, dA);
            } else {
#pragma unroll
                for (int s = 0; s < DS; s++) dA[s] = __expf(dt * Av[s]);
            }
            float p = 0.f;
#pragma unroll
            for (int s = 0; s < DS; s++) {
                h[s] = dA[s]*h[s] + cdt*Bv[s];
                p += h[s]*Cv[s];
            }
            yp[(size_t)t*DI] = (p + Dd*xv) * silu_fast(zv);
        }
    }
}

// ---------------- final: rmsnorm + layernorm + output layout ----------------
__global__ void final_kernel(const float* __restrict__ wf,
                             const float* __restrict__ lw,
                             const float* __restrict__ lb,
                             float* __restrict__ out) {
    int row = blockIdx.x, c = threadIdx.x;
    size_t idx = (size_t)row*DM + c;
    float h = g_res[idx];           // residual already includes final hidden
    float ss = block_sum_256(h*h);
    h = h * rsqrtf(ss * (1.f/DM) + 1e-5f) * wf[c];
    float mu = block_sum_256(h) * (1.f/DM);
    float hm = h - mu;
    float var = block_sum_256(hm*hm) * (1.f/DM);
    float o = hm * rsqrtf(var + 1e-5f) * lw[c] + lb[c];
    int b = row / LL, t = row % LL;
    size_t dst = (t < LL-1) ? ((size_t)(b*(LL-1) + t)*DM + c)
                            : ((size_t)BB*(LL-1)*DM + (size_t)b*DM + c);
    out[dst] = o;
}

// ---------------- host launch -----------------------------------------------
static float* sym_addr(const void* sym) {
    void* p = nullptr;
    cudaGetSymbolAddress(&p, sym);
    return (float*)p;
}

extern "C" void kernel_launch(void* const* d_in, const int* in_sizes, int n_in,
                              void* d_out, int out_size) {
    const float* tokens = (const float*)d_in[0];
    const void*  mask   = d_in[1];
    const float* in_w   = (const float*)d_in[2];
    const float* conv_w = (const float*)d_in[3];
    const float* conv_b = (const float*)d_in[4];
    const float* x_w    = (const float*)d_in[5];
    const float* dtw    = (const float*)d_in[6];
    const float* dtb    = (const float*)d_in[7];
    const float* Alog   = (const float*)d_in[8];
    const float* Dsk    = (const float*)d_in[9];
    const float* out_w  = (const float*)d_in[10];
    const float* norm_w = (const float*)d_in[11];
    const float* norm_f = (const float*)d_in[12];
    const float* ln_w   = (const float*)d_in[13];
    const float* ln_b   = (const float*)d_in[14];
    float* out = (float*)d_out;

    float* p_norm = sym_addr(g_norm);
    float* p_xz   = sym_addr(g_xz);
    float* p_y    = sym_addr(g_y);

    detect_mask_kernel<<<1, 32>>>((const unsigned char*)mask);
    {
        int n = DEPTH*DI*DS;
        check_A_kernel<<<(n + 255)/256, 256>>>(Alog, n);
    }
    gather_idx_kernel<<<BB, NN>>>(mask);
    gather_copy_kernel<<<MROWS, DM>>>(tokens);

    dim3 sgrid(DI/128, KCH, BB);

    for (int l = 0; l < DEPTH; l++) {
        // norm = rmsnorm(res) * w
        rmsnorm_kernel<<<MROWS/8, 256>>>(norm_w + (size_t)l*DM);

        // xz = norm @ in_w^T   (3072 x 1024 x 256)
        {
            dim3 grid((2*DI)/128, MROWS/128);
            sgemm_nt<128,128><<<grid, 256>>>(p_norm, in_w + (size_t)l*2*DI*DM,
                                             p_xz, MROWS, 2*DI, DM);
        }

        // fused conv+silu+x_proj: writes g_xc and g_xdbl (32-row tiles)
        xproj_conv_kernel<<<MROWS/32, 256>>>(x_w + (size_t)l*48*DI,
                                             conv_w + (size_t)l*DI*4,
                                             conv_b + (size_t)l*DI);

        // scan: S1 (P,Q + packed stream), hin (chunk-prefix), S2 (rescan+gate)
        scan_s1_kernel<<<sgrid, 128>>>(Alog + (size_t)l*DI*DS,
                                       dtw  + (size_t)l*DI*DTR,
                                       dtb  + (size_t)l*DI);
        hin_kernel<<<(BB*DI*DS)/256, 256>>>();
        scan_s2_kernel<<<sgrid, 128>>>(Alog + (size_t)l*DI*DS,
                                       Dsk  + (size_t)l*DI);

        // res += y @ out_w^T   (residual update fused into epilogue)
        {
            dim3 grid(DM/64, MROWS/64);
            outproj_gemm<<<grid, 256>>>(p_y, out_w + (size_t)l*DM*DI);
        }
    }

    final_kernel<<<MROWS, DM>>>(norm_f, ln_w, ln_b, out);
}